// round 1
// baseline (speedup 1.0000x reference)
#include <cuda_runtime.h>
#include <math.h>

#define DIM   240
#define SEQ   1024
#define NB    240
#define NROW  (NB*SEQ)   // 245760

typedef unsigned long long ull;

// -------- device scratch (allocation-free rule: static __device__ globals) ----
__device__ float g_WxT[DIM*DIM];
__device__ float g_WgT[DIM*DIM];
__device__ float g_WoT[DIM*DIM];
__device__ float g_M  [DIM*DIM];            // M[e][f] = decay * sum_d Wk[d,e]*Wv[d,f]
__device__ float g_Xc [(size_t)NROW*DIM];   // cumsum of x over s  (236 MB)
__device__ float g_diagT[SEQ*DIM];          // diagT[s*240 + b]

// -------- packed fp32x2 helpers (Blackwell FFMA2: 2x fp32 throughput) --------
__device__ __forceinline__ ull pack2(float lo, float hi){
    ull r; asm("mov.b64 %0, {%1, %2};" : "=l"(r) : "f"(lo), "f"(hi)); return r;
}
__device__ __forceinline__ void unpack2(ull p, float& lo, float& hi){
    asm("mov.b64 {%0, %1}, %2;" : "=f"(lo), "=f"(hi) : "l"(p));
}
__device__ __forceinline__ void fma2(ull& d, ull a, ull b){
    asm("fma.rn.f32x2 %0, %1, %2, %0;" : "+l"(d) : "l"(a), "l"(b));
}

// ============================ prep kernels ===================================

// Transpose Wx, Wg, Wo ([out,in] -> [in,out]) so GEMM inner loops read coalesced.
__global__ void transpose3_kernel(const float* __restrict__ Wx,
                                  const float* __restrict__ Wg,
                                  const float* __restrict__ Wo){
    __shared__ float tile[32][33];
    const float* src; float* dst;
    if      (blockIdx.z == 0){ src = Wx; dst = g_WxT; }
    else if (blockIdx.z == 1){ src = Wg; dst = g_WgT; }
    else                     { src = Wo; dst = g_WoT; }
    int gx = blockIdx.x*32 + threadIdx.x;       // src col (e)
    int gy = blockIdx.y*32 + threadIdx.y;       // src row (d)
    #pragma unroll
    for (int i = 0; i < 32; i += 8){
        int yy = gy + i;
        if (gx < DIM && yy < DIM) tile[threadIdx.y+i][threadIdx.x] = src[yy*DIM + gx];
    }
    __syncthreads();
    int tx = blockIdx.y*32 + threadIdx.x;       // dst col (d)
    int ty = blockIdx.x*32 + threadIdx.y;       // dst row (e)
    #pragma unroll
    for (int i = 0; i < 32; i += 8){
        int yy = ty + i;
        if (tx < DIM && yy < DIM) dst[yy*DIM + tx] = tile[threadIdx.x][threadIdx.y+i];
    }
}

// M[e][f] = decay * sum_d Wk[d,e] * Wv[d,f]   (240x240x240, trivial cost)
__global__ void compute_M_kernel(const float* __restrict__ Wk,
                                 const float* __restrict__ Wv,
                                 const float* __restrict__ dmask){
    __shared__ float As[16][17], Bs[16][17];
    int e = blockIdx.y*16 + threadIdx.y;
    int f = blockIdx.x*16 + threadIdx.x;
    float acc = 0.f;
    for (int d0 = 0; d0 < DIM; d0 += 16){
        As[threadIdx.y][threadIdx.x] = Wk[(d0+threadIdx.y)*DIM + blockIdx.y*16 + threadIdx.x];
        Bs[threadIdx.y][threadIdx.x] = Wv[(d0+threadIdx.y)*DIM + f];
        __syncthreads();
        #pragma unroll
        for (int dd = 0; dd < 16; dd++)
            acc += As[dd][threadIdx.y] * Bs[dd][threadIdx.x];
        __syncthreads();
    }
    float decay = dmask[SEQ];   // decay_mask[1][0], inside the tril (== 0.9)
    g_M[e*DIM + f] = acc * decay;
}

// Inclusive cumsum of x over s, per (b, d) column. Memory bound.
__global__ void cumsum_kernel(const float* __restrict__ x){
    int idx = blockIdx.x*blockDim.x + threadIdx.x;      // b*DIM + d
    if (idx >= NB*DIM) return;
    int b = idx / DIM, d = idx % DIM;
    const float* xp = x    + (size_t)b*SEQ*DIM + d;
    float*       cp = g_Xc + (size_t)b*SEQ*DIM + d;
    float acc = 0.f;
    for (int s = 0; s < SEQ; s += 8){
        float v[8];
        #pragma unroll
        for (int i = 0; i < 8; i++) v[i] = xp[(size_t)(s+i)*DIM];
        #pragma unroll
        for (int i = 0; i < 8; i++){ acc += v[i]; cp[(size_t)(s+i)*DIM] = acc; }
    }
}

// ======================= K2: diag via fused P-GEMM + dot =====================
// Block: 64 rows x 240 cols, 240 threads, thread tile 8x8 (cols packed f32x2).
__global__ void __launch_bounds__(240, 1)
diag_kernel(const float* __restrict__ x){
    __shared__ __align__(16) float xsT[16][68];     // [e-in-chunk][row]
    __shared__ __align__(16) float Ms [16][DIM];
    __shared__ float psum[64][32];

    int row0 = blockIdx.x * 64;
    int tid  = threadIdx.x;
    int rt = tid / 30, ct = tid % 30;
    int r0 = rt*8, c0 = ct*8;

    ull acc[8][4];
    #pragma unroll
    for (int i = 0; i < 8; i++)
        #pragma unroll
        for (int j = 0; j < 4; j++) acc[i][j] = 0ull;

    for (int e0 = 0; e0 < DIM; e0 += 16){
        // stage x chunk transposed: xsT[ee][r] = x[row0+r][e0+ee]
        for (int i = tid; i < 256; i += 240){
            int r = i >> 2, q = i & 3;
            float4 xv = *(const float4*)(x + (size_t)(row0+r)*DIM + e0 + q*4);
            xsT[q*4+0][r] = xv.x; xsT[q*4+1][r] = xv.y;
            xsT[q*4+2][r] = xv.z; xsT[q*4+3][r] = xv.w;
        }
        // stage M chunk
        for (int i = tid; i < 960; i += 240){
            int ee = i/60, q = i%60;
            *(float4*)&Ms[ee][q*4] = *(const float4*)(g_M + (e0+ee)*DIM + q*4);
        }
        __syncthreads();
        #pragma unroll
        for (int ee = 0; ee < 16; ee++){
            float4 a0 = *(const float4*)&xsT[ee][r0];
            float4 a1 = *(const float4*)&xsT[ee][r0+4];
            ull ad[8];
            ad[0]=pack2(a0.x,a0.x); ad[1]=pack2(a0.y,a0.y);
            ad[2]=pack2(a0.z,a0.z); ad[3]=pack2(a0.w,a0.w);
            ad[4]=pack2(a1.x,a1.x); ad[5]=pack2(a1.y,a1.y);
            ad[6]=pack2(a1.z,a1.z); ad[7]=pack2(a1.w,a1.w);
            const ull* bp = (const ull*)&Ms[ee][c0];
            ull b0=bp[0], b1=bp[1], b2=bp[2], b3=bp[3];
            #pragma unroll
            for (int i = 0; i < 8; i++){
                fma2(acc[i][0], ad[i], b0);
                fma2(acc[i][1], ad[i], b1);
                fma2(acc[i][2], ad[i], b2);
                fma2(acc[i][3], ad[i], b3);
            }
        }
        __syncthreads();
    }

    // dot P-tile with Xc, reduce across col-threads via smem (deterministic)
    #pragma unroll
    for (int i = 0; i < 8; i++){
        int row = row0 + r0 + i;
        float4 c4a = *(const float4*)(g_Xc + (size_t)row*DIM + c0);
        float4 c4b = *(const float4*)(g_Xc + (size_t)row*DIM + c0 + 4);
        float lo, hi, s = 0.f;
        unpack2(acc[i][0], lo, hi); s += lo*c4a.x + hi*c4a.y;
        unpack2(acc[i][1], lo, hi); s += lo*c4a.z + hi*c4a.w;
        unpack2(acc[i][2], lo, hi); s += lo*c4b.x + hi*c4b.y;
        unpack2(acc[i][3], lo, hi); s += lo*c4b.z + hi*c4b.w;
        psum[r0+i][ct] = s;
    }
    __syncthreads();
    if (tid < 64){
        float s = 0.f;
        #pragma unroll
        for (int c = 0; c < 30; c++) s += psum[tid][c];
        int row = row0 + tid;
        int b = row >> 10, sidx = row & (SEQ-1);
        g_diagT[sidx*DIM + b] = s;
    }
}

// ====== K3: fused  out = ((x@WxT) * sigmoid(x@WgT) * diag[d,s]) @ WoT + bo ===
__global__ void __launch_bounds__(240, 1)
final_kernel(const float* __restrict__ x,
             const float* __restrict__ bo,
             float* __restrict__ out){
    __shared__ __align__(16) float xsT[16][68];
    __shared__ __align__(16) float Wa [16][DIM];
    __shared__ __align__(16) float Wb [16][DIM];
    __shared__ __align__(16) float ys [64][248];

    int row0 = blockIdx.x * 64;
    int tid  = threadIdx.x;
    int rt = tid / 30, ct = tid % 30;
    int r0 = rt*8, c0 = ct*8;

    ull ax[8][4], ag[8][4];
    #pragma unroll
    for (int i = 0; i < 8; i++)
        #pragma unroll
        for (int j = 0; j < 4; j++){ ax[i][j] = 0ull; ag[i][j] = 0ull; }

    // ---- GEMM1: xk = x@WxT, gpre = x@WgT (shared A operand) ----
    for (int e0 = 0; e0 < DIM; e0 += 16){
        for (int i = tid; i < 256; i += 240){
            int r = i >> 2, q = i & 3;
            float4 xv = *(const float4*)(x + (size_t)(row0+r)*DIM + e0 + q*4);
            xsT[q*4+0][r] = xv.x; xsT[q*4+1][r] = xv.y;
            xsT[q*4+2][r] = xv.z; xsT[q*4+3][r] = xv.w;
        }
        for (int i = tid; i < 960; i += 240){
            int ee = i/60, q = i%60;
            *(float4*)&Wa[ee][q*4] = *(const float4*)(g_WxT + (e0+ee)*DIM + q*4);
            *(float4*)&Wb[ee][q*4] = *(const float4*)(g_WgT + (e0+ee)*DIM + q*4);
        }
        __syncthreads();
        #pragma unroll
        for (int ee = 0; ee < 16; ee++){
            float4 a0 = *(const float4*)&xsT[ee][r0];
            float4 a1 = *(const float4*)&xsT[ee][r0+4];
            ull ad[8];
            ad[0]=pack2(a0.x,a0.x); ad[1]=pack2(a0.y,a0.y);
            ad[2]=pack2(a0.z,a0.z); ad[3]=pack2(a0.w,a0.w);
            ad[4]=pack2(a1.x,a1.x); ad[5]=pack2(a1.y,a1.y);
            ad[6]=pack2(a1.z,a1.z); ad[7]=pack2(a1.w,a1.w);
            const ull* bxp = (const ull*)&Wa[ee][c0];
            const ull* bgp = (const ull*)&Wb[ee][c0];
            ull bx0=bxp[0], bx1=bxp[1], bx2=bxp[2], bx3=bxp[3];
            ull bg0=bgp[0], bg1=bgp[1], bg2=bgp[2], bg3=bgp[3];
            #pragma unroll
            for (int i = 0; i < 8; i++){
                fma2(ax[i][0], ad[i], bx0); fma2(ax[i][1], ad[i], bx1);
                fma2(ax[i][2], ad[i], bx2); fma2(ax[i][3], ad[i], bx3);
                fma2(ag[i][0], ad[i], bg0); fma2(ag[i][1], ad[i], bg1);
                fma2(ag[i][2], ad[i], bg2); fma2(ag[i][3], ad[i], bg3);
            }
        }
        __syncthreads();
    }

    // ---- epilogue 1: y = xk * sigmoid(gpre) * diag[d, s]  -> smem ----
    #pragma unroll
    for (int i = 0; i < 8; i++){
        int row = row0 + r0 + i;
        int s   = row & (SEQ-1);
        const float* dgp = g_diagT + s*DIM + c0;
        float4 d0 = *(const float4*)dgp;
        float4 d1 = *(const float4*)(dgp + 4);
        float xv[8], gv[8];
        unpack2(ax[i][0], xv[0], xv[1]); unpack2(ax[i][1], xv[2], xv[3]);
        unpack2(ax[i][2], xv[4], xv[5]); unpack2(ax[i][3], xv[6], xv[7]);
        unpack2(ag[i][0], gv[0], gv[1]); unpack2(ag[i][1], gv[2], gv[3]);
        unpack2(ag[i][2], gv[4], gv[5]); unpack2(ag[i][3], gv[6], gv[7]);
        float y[8];
        #pragma unroll
        for (int k = 0; k < 8; k++) y[k] = xv[k] / (1.f + expf(-gv[k]));
        y[0]*=d0.x; y[1]*=d0.y; y[2]*=d0.z; y[3]*=d0.w;
        y[4]*=d1.x; y[5]*=d1.y; y[6]*=d1.z; y[7]*=d1.w;
        *(float4*)&ys[r0+i][c0]   = make_float4(y[0],y[1],y[2],y[3]);
        *(float4*)&ys[r0+i][c0+4] = make_float4(y[4],y[5],y[6],y[7]);
    }

    // ---- GEMM2: out = y @ WoT + bo ----
    ull ao[8][4];
    #pragma unroll
    for (int i = 0; i < 8; i++)
        #pragma unroll
        for (int j = 0; j < 4; j++) ao[i][j] = 0ull;

    for (int d0 = 0; d0 < DIM; d0 += 16){
        for (int i = tid; i < 960; i += 240){
            int dd = i/60, q = i%60;
            *(float4*)&Wa[dd][q*4] = *(const float4*)(g_WoT + (d0+dd)*DIM + q*4);
        }
        __syncthreads();
        #pragma unroll
        for (int dd = 0; dd < 16; dd++){
            ull ad[8];
            #pragma unroll
            for (int i = 0; i < 8; i++){
                float v = ys[r0+i][d0+dd];
                ad[i] = pack2(v, v);
            }
            const ull* bp = (const ull*)&Wa[dd][c0];
            ull b0=bp[0], b1=bp[1], b2=bp[2], b3=bp[3];
            #pragma unroll
            for (int i = 0; i < 8; i++){
                fma2(ao[i][0], ad[i], b0);
                fma2(ao[i][1], ad[i], b1);
                fma2(ao[i][2], ad[i], b2);
                fma2(ao[i][3], ad[i], b3);
            }
        }
        __syncthreads();
    }

    float4 bv0 = *(const float4*)(bo + c0);
    float4 bv1 = *(const float4*)(bo + c0 + 4);
    #pragma unroll
    for (int i = 0; i < 8; i++){
        int row = row0 + r0 + i;
        float o[8];
        unpack2(ao[i][0], o[0], o[1]); unpack2(ao[i][1], o[2], o[3]);
        unpack2(ao[i][2], o[4], o[5]); unpack2(ao[i][3], o[6], o[7]);
        float4 w0 = make_float4(o[0]+bv0.x, o[1]+bv0.y, o[2]+bv0.z, o[3]+bv0.w);
        float4 w1 = make_float4(o[4]+bv1.x, o[5]+bv1.y, o[6]+bv1.z, o[7]+bv1.w);
        *(float4*)(out + (size_t)row*DIM + c0)     = w0;
        *(float4*)(out + (size_t)row*DIM + c0 + 4) = w1;
    }
}

// ================================ launch =====================================
extern "C" void kernel_launch(void* const* d_in, const int* in_sizes, int n_in,
                              void* d_out, int out_size){
    const float* x     = (const float*)d_in[0];
    const float* Wx    = (const float*)d_in[1];
    const float* Wk    = (const float*)d_in[2];
    const float* Wv    = (const float*)d_in[3];
    const float* Wg    = (const float*)d_in[4];
    const float* Wo    = (const float*)d_in[5];
    const float* bo    = (const float*)d_in[6];
    const float* dmask = (const float*)d_in[7];
    float* out = (float*)d_out;
    (void)in_sizes; (void)n_in; (void)out_size;

    transpose3_kernel<<<dim3(8,8,3), dim3(32,8)>>>(Wx, Wg, Wo);
    compute_M_kernel<<<dim3(15,15), dim3(16,16)>>>(Wk, Wv, dmask);
    cumsum_kernel<<<(NB*DIM + 255)/256, 256>>>(x);
    diag_kernel<<<NROW/64, 240>>>(x);
    final_kernel<<<NROW/64, 240>>>(x, bo, out);
}

// round 3
// speedup vs baseline: 3.9753x; 3.9753x over previous
#include <cuda_runtime.h>
#include <math.h>
#include <stdint.h>

#define DIM    240
#define SEQ    1024
#define NB     240
#define NROW   (NB*SEQ)      // 245760
#define MTILE  128
#define KC     64
#define NCHUNK 4
#define THREADS 256

// idesc: dtype=f32(1<<4), atype=tf32(2<<7), btype=tf32(2<<10), N=240(30<<17), M=128(8<<24)
#define IDESC ((1u<<4)|(2u<<7)|(2u<<10)|(30u<<17)|(8u<<24))

// tcgen05 is an arch-SPECIFIC feature: only emit it in the sm_103a/sm_100a
// cubin pass. The compute_103 PTX fallback pass compiles plain-fp32 bodies.
#if !defined(__CUDA_ARCH__) || defined(__CUDA_ARCH_FEAT_SM103_ALL) || defined(__CUDA_ARCH_FEAT_SM100_ALL) || defined(__CUDA_ARCH_FEAT_SM101_ALL)
#define HAS_TC 1
#else
#define HAS_TC 0
#endif

// ---------------- device scratch ----------------
__device__ float g_MT  [DIM*256];              // MT[f][e] (e padded to 256 with zeros)
__device__ float g_Xc  [(size_t)NROW*DIM];     // cumsum of x over s
__device__ float g_diagT[SEQ*DIM];             // diagT[s*240 + b]

// ---------------- PTX helpers ----------------
__device__ __forceinline__ uint32_t smem_u32(const void* p){
    uint32_t a;
    asm("{ .reg .u64 t; cvta.to.shared.u64 t, %1; cvt.u32.u64 %0, t; }" : "=r"(a) : "l"(p));
    return a;
}
__device__ __forceinline__ float sigf(float v){ return 1.f / (1.f + expf(-v)); }

#if HAS_TC
__device__ __forceinline__ uint32_t elect_one(){
    uint32_t p;
    asm volatile("{ .reg .pred p; elect.sync _|p, 0xFFFFFFFF; selp.b32 %0, 1, 0, p; }" : "=r"(p));
    return p;
}
__device__ __forceinline__ uint64_t sdesc(uint32_t addr){
    return ((uint64_t)2 << 61) | ((uint64_t)1 << 46) | ((uint64_t)64 << 32)
         | ((uint64_t)1 << 16) | ((uint64_t)(addr >> 4) & 0x3FFF);
}
__device__ __forceinline__ void mma_tf32(uint32_t d, uint64_t a, uint64_t b, uint32_t id, uint32_t en){
    asm volatile(
        "{\n\t.reg .pred p;\n\tsetp.ne.u32 p, %5, 0;\n\t"
        "tcgen05.mma.cta_group::1.kind::tf32 [%0], %1, %2, %3, {%4, %4, %4, %4}, p;\n\t}"
        :: "r"(d), "l"(a), "l"(b), "r"(id), "r"(0u), "r"(en) : "memory");
}
__device__ __forceinline__ void mbar_wait(uint32_t mbar, uint32_t phase){
    asm volatile(
        "{\n\t.reg .pred P;\n\t"
        "W%=:\n\t"
        "mbarrier.try_wait.parity.acquire.cta.shared::cta.b64 P, [%0], %1, 0x989680;\n\t"
        "@P bra.uni D%=;\n\t"
        "bra.uni W%=;\n\t"
        "D%=:\n\t}"
        :: "r"(mbar), "r"(phase) : "memory");
}
#define TC_ALLOC(sa, n)  asm volatile("tcgen05.alloc.cta_group::1.sync.aligned.shared::cta.b32 [%0], %1;" :: "r"(sa), "r"(n) : "memory")
#define TC_RELINQ()      asm volatile("tcgen05.relinquish_alloc_permit.cta_group::1.sync.aligned;")
#define TC_DEALLOC(t, n) asm volatile("tcgen05.dealloc.cta_group::1.sync.aligned.b32 %0, %1;" :: "r"(t), "r"(n))
#define TC_COMMIT(mb)    asm volatile("tcgen05.commit.cta_group::1.mbarrier::arrive::one.shared::cluster.b64 [%0];" :: "r"(mb) : "memory")
#define TC_WAIT_LD()     asm volatile("tcgen05.wait::ld.sync.aligned;" ::: "memory")
#define TC_FENCE_AFTER()  asm volatile("tcgen05.fence::after_thread_sync;" ::: "memory")
#define TC_FENCE_BEFORE() asm volatile("tcgen05.fence::before_thread_sync;" ::: "memory")
#define FENCE_ASYNC()    asm volatile("fence.proxy.async.shared::cta;" ::: "memory")
#define MBAR_INIT(a)     asm volatile("mbarrier.init.shared.b64 [%0], 1;" :: "r"(a) : "memory")

#define LDTM32(r, a) \
    asm volatile( \
        "tcgen05.ld.sync.aligned.32x32b.x32.b32 " \
        "{%0, %1, %2, %3, %4, %5, %6, %7, " \
        " %8, %9, %10, %11, %12, %13, %14, %15, " \
        " %16, %17, %18, %19, %20, %21, %22, %23, " \
        " %24, %25, %26, %27, %28, %29, %30, %31}, [%32];" \
        : "=r"((r)[0]),  "=r"((r)[1]),  "=r"((r)[2]),  "=r"((r)[3]), \
          "=r"((r)[4]),  "=r"((r)[5]),  "=r"((r)[6]),  "=r"((r)[7]), \
          "=r"((r)[8]),  "=r"((r)[9]),  "=r"((r)[10]), "=r"((r)[11]), \
          "=r"((r)[12]), "=r"((r)[13]), "=r"((r)[14]), "=r"((r)[15]), \
          "=r"((r)[16]), "=r"((r)[17]), "=r"((r)[18]), "=r"((r)[19]), \
          "=r"((r)[20]), "=r"((r)[21]), "=r"((r)[22]), "=r"((r)[23]), \
          "=r"((r)[24]), "=r"((r)[25]), "=r"((r)[26]), "=r"((r)[27]), \
          "=r"((r)[28]), "=r"((r)[29]), "=r"((r)[30]), "=r"((r)[31]) \
        : "r"(a))

#define LDTM16(r, a) \
    asm volatile( \
        "tcgen05.ld.sync.aligned.32x32b.x16.b32 " \
        "{%0, %1, %2, %3, %4, %5, %6, %7, " \
        " %8, %9, %10, %11, %12, %13, %14, %15}, [%16];" \
        : "=r"((r)[0]),  "=r"((r)[1]),  "=r"((r)[2]),  "=r"((r)[3]), \
          "=r"((r)[4]),  "=r"((r)[5]),  "=r"((r)[6]),  "=r"((r)[7]), \
          "=r"((r)[8]),  "=r"((r)[9]),  "=r"((r)[10]), "=r"((r)[11]), \
          "=r"((r)[12]), "=r"((r)[13]), "=r"((r)[14]), "=r"((r)[15]) \
        : "r"(a))

// ---------------- swizzled blocked-atom addressing (atom = 8 rows x 128B) ---
__device__ __forceinline__ uint32_t swz(uint32_t off){ return off ^ ((off >> 3) & 0x70); }
// A / Y tiles: 128 rows -> 16 atom-rows per atom-column
__device__ __forceinline__ uint32_t a_off(int r, int k){
    uint32_t o = ((uint32_t)((k >> 5) * 16 + (r >> 3)) << 10) + ((uint32_t)(r & 7) << 7) + ((uint32_t)(k & 31) << 2);
    return swz(o);
}
// B tiles: 240 rows -> 30 atom-rows per atom-column
__device__ __forceinline__ uint32_t b_off(int f, int k){
    uint32_t o = ((uint32_t)((k >> 5) * 30 + (f >> 3)) << 10) + ((uint32_t)(f & 7) << 7) + ((uint32_t)(k & 31) << 2);
    return swz(o);
}
__device__ __forceinline__ void sts_tf32x4(uint32_t addr, float4 v){
    uint32_t a, b, c, d;
    asm("cvt.rna.tf32.f32 %0, %1;" : "=r"(a) : "f"(v.x));
    asm("cvt.rna.tf32.f32 %0, %1;" : "=r"(b) : "f"(v.y));
    asm("cvt.rna.tf32.f32 %0, %1;" : "=r"(c) : "f"(v.z));
    asm("cvt.rna.tf32.f32 %0, %1;" : "=r"(d) : "f"(v.w));
    asm volatile("st.shared.v4.b32 [%0], {%1, %2, %3, %4};" :: "r"(addr), "r"(a), "r"(b), "r"(c), "r"(d) : "memory");
}

// ---------------- staging ----------------
__device__ __forceinline__ void stageA(uint32_t sa, const float* __restrict__ x,
                                       int row0, int ch, int tid, int nthr){
    for (int i = tid; i < MTILE*16; i += nthr){
        int r = i >> 4, q = i & 15;
        int gk = ch*KC + q*4;
        float4 v = make_float4(0.f, 0.f, 0.f, 0.f);
        if (gk < DIM) v = *(const float4*)(x + (size_t)(row0 + r)*DIM + gk);
        sts_tf32x4(sa + a_off(r, q*4), v);
    }
}
__device__ __forceinline__ void stageB(uint32_t sa, const float* __restrict__ W,
                                       int ch, int tid, int nthr){
    for (int i = tid; i < DIM*16; i += nthr){
        int f = i >> 4, q = i & 15;
        int gk = ch*KC + q*4;
        float4 v = make_float4(0.f, 0.f, 0.f, 0.f);
        if (gk < DIM) v = *(const float4*)(W + (size_t)f*DIM + gk);
        sts_tf32x4(sa + b_off(f, q*4), v);
    }
}
__device__ __forceinline__ void stageB_MT(uint32_t sa, int ch, int tid, int nthr){
    for (int i = tid; i < DIM*16; i += nthr){
        int f = i >> 4, q = i & 15;
        int gk = ch*KC + q*4;                 // < 256 always; MT is padded
        float4 v = *(const float4*)(g_MT + (size_t)f*256 + gk);
        sts_tf32x4(sa + b_off(f, q*4), v);
    }
}
#endif  // HAS_TC

// ---------------- prep kernels (arch-neutral) ----------------
// MT[f][e] = decay * sum_d Wv[d,f] * Wk[d,e]   (e padded to 256)
__global__ void compute_MT_kernel(const float* __restrict__ Wk,
                                  const float* __restrict__ Wv,
                                  const float* __restrict__ dmask){
    __shared__ float As[16][17], Bs[16][17];
    int e = blockIdx.x*16 + threadIdx.x;   // 0..255
    float acc = 0.f;
    for (int d0 = 0; d0 < DIM; d0 += 16){
        As[threadIdx.y][threadIdx.x] = Wv[(d0 + threadIdx.y)*DIM + blockIdx.y*16 + threadIdx.x];
        Bs[threadIdx.y][threadIdx.x] = (e < DIM) ? Wk[(d0 + threadIdx.y)*DIM + e] : 0.f;
        __syncthreads();
        #pragma unroll
        for (int dd = 0; dd < 16; dd++)
            acc += As[dd][threadIdx.y] * Bs[dd][threadIdx.x];
        __syncthreads();
    }
    int f = blockIdx.y*16 + threadIdx.y;   // 0..239
    float decay = dmask[SEQ];              // decay_mask[1][0] == 0.9
    g_MT[(size_t)f*256 + e] = (e < DIM) ? acc * decay : 0.f;
}

// inclusive cumsum of x over s per (b,d)
__global__ void cumsum_kernel(const float* __restrict__ x){
    int idx = blockIdx.x*blockDim.x + threadIdx.x;
    if (idx >= NB*DIM) return;
    int b = idx / DIM, d = idx % DIM;
    const float* xp = x    + (size_t)b*SEQ*DIM + d;
    float*       cp = g_Xc + (size_t)b*SEQ*DIM + d;
    float acc = 0.f;
    for (int s = 0; s < SEQ; s += 8){
        float v[8];
        #pragma unroll
        for (int i = 0; i < 8; i++) v[i] = xp[(size_t)(s + i)*DIM];
        #pragma unroll
        for (int i = 0; i < 8; i++){ acc += v[i]; cp[(size_t)(s + i)*DIM] = acc; }
    }
}

// ---------------- K1: diag via tcgen05 P = x @ MT^T, then TMEM dot with Xc --
#define DG_A   1024u
#define DG_BM  (DG_A + 32768u)
#define DG_XC  (DG_BM + 61440u)
#define DG_SMEM (DG_XC + 128u*244u*4u)   // 220160

__global__ void __launch_bounds__(THREADS, 1) __cluster_dims__(1, 1, 1)
diag_tc(const float* __restrict__ x){
#if HAS_TC
    extern __shared__ char smem[];
    uint32_t sb = smem_u32(smem);
    const int tid = threadIdx.x;
    const int wid = tid >> 5, lane = tid & 31;
    const int row0 = blockIdx.x * MTILE;
    const uint32_t MBAR = sb + 8;

    if (wid == 0){ TC_ALLOC(sb + 0, 512); TC_RELINQ(); }
    if (tid == 0){ MBAR_INIT(MBAR); }
    __syncthreads();
    uint32_t tmem;
    asm volatile("ld.shared.b32 %0, [%1];" : "=r"(tmem) : "r"(sb + 0));

    // stage Xc tile [128][244] (coalesced)
    float* xcs = (float*)(smem + DG_XC);
    for (int i = tid; i < MTILE*60; i += THREADS){
        int r = i / 60, q = i % 60;
        float4 v = *(const float4*)(g_Xc + (size_t)(row0 + r)*DIM + q*4);
        *(float4*)(xcs + r*244 + q*4) = v;
    }

    uint32_t parity = 0;
    for (int ch = 0; ch < NCHUNK; ch++){
        if (ch){ mbar_wait(MBAR, parity); parity ^= 1; }
        stageA(sb + DG_A, x, row0, ch, tid, THREADS);
        stageB_MT(sb + DG_BM, ch, tid, THREADS);
        FENCE_ASYNC();
        __syncthreads();
        if (wid == 0 && elect_one()){
            uint64_t ad = sdesc(sb + DG_A), bd = sdesc(sb + DG_BM);
            #pragma unroll
            for (int ks = 0; ks < 8; ks++){
                uint64_t ao   = (uint64_t)((ks >> 2)*1024 + (ks & 3)*2);
                uint64_t bofs = (uint64_t)((ks >> 2)*1920 + (ks & 3)*2);
                mma_tf32(tmem, ad + ao, bd + bofs, IDESC, (ch | ks) ? 1u : 0u);
            }
            TC_COMMIT(MBAR);
        }
    }
    mbar_wait(MBAR, parity); parity ^= 1;
    TC_FENCE_AFTER();

    if (wid < 4){
        int rl = wid*32 + lane;
        int row = row0 + rl;
        uint32_t woff = (uint32_t)wid << 21;
        float acc = 0.f;
        for (int c0 = 0; c0 < 240; c0 += 32){
            uint32_t pr[32];
            if (c0 < 224){
                LDTM32(pr, tmem + c0 + woff);
                TC_WAIT_LD();
                #pragma unroll
                for (int j = 0; j < 8; j++){
                    float4 c4 = *(const float4*)(xcs + rl*244 + c0 + j*4);
                    acc += __uint_as_float(pr[j*4+0])*c4.x + __uint_as_float(pr[j*4+1])*c4.y
                         + __uint_as_float(pr[j*4+2])*c4.z + __uint_as_float(pr[j*4+3])*c4.w;
                }
            } else {
                LDTM16(pr, tmem + c0 + woff);
                TC_WAIT_LD();
                #pragma unroll
                for (int j = 0; j < 4; j++){
                    float4 c4 = *(const float4*)(xcs + rl*244 + c0 + j*4);
                    acc += __uint_as_float(pr[j*4+0])*c4.x + __uint_as_float(pr[j*4+1])*c4.y
                         + __uint_as_float(pr[j*4+2])*c4.z + __uint_as_float(pr[j*4+3])*c4.w;
                }
            }
        }
        int b = row >> 10, s = row & (SEQ - 1);
        g_diagT[(size_t)s*DIM + b] = acc;
    }
    __syncthreads();
    if (wid == 0) TC_DEALLOC(tmem, 512);
#else
    // plain-fp32 fallback (compute_103 PTX pass; not executed on GB300)
    const int tid = threadIdx.x;
    const int row0 = blockIdx.x * MTILE;
    __shared__ float red[THREADS];
    int r = tid >> 1, half = tid & 1;
    int row = row0 + r;
    float acc = 0.f;
    for (int f = half*120; f < half*120 + 120; f++){
        float p = 0.f;
        for (int e = 0; e < DIM; e++) p += x[(size_t)row*DIM + e] * g_MT[(size_t)f*256 + e];
        acc += p * g_Xc[(size_t)row*DIM + f];
    }
    red[tid] = acc;
    __syncthreads();
    if (half == 0){
        int b = row >> 10, s = row & (SEQ - 1);
        g_diagT[(size_t)s*DIM + b] = red[tid] + red[tid + 1];
    }
#endif
}

// ---------------- K2: fused final (Wx/Wg GEMMs -> gate -> Wo GEMM) ----------
#define FN_A   1024u
#define FN_BX  (FN_A + 32768u)
#define FN_BG  (FN_BX + 61440u)          // GEMM1 staging ends at 156672
#define FN_Y   1024u                      // reuse (128KB, tf32 blocked atoms)
#define FN_WO  (FN_Y + 131072u)           // 132096
#define FN_OUT 1024u                      // reuse after final MMA wait
#define FN_SMEM (FN_WO + 61440u)          // 193536

__global__ void __launch_bounds__(THREADS, 1) __cluster_dims__(1, 1, 1)
final_tc(const float* __restrict__ x,  const float* __restrict__ Wx,
         const float* __restrict__ Wg, const float* __restrict__ Wo,
         const float* __restrict__ bo, float* __restrict__ out){
#if HAS_TC
    extern __shared__ char smem[];
    uint32_t sb = smem_u32(smem);
    const int tid = threadIdx.x;
    const int wid = tid >> 5, lane = tid & 31;
    const int row0 = blockIdx.x * MTILE;
    const uint32_t MBAR = sb + 8;

    if (wid == 0){ TC_ALLOC(sb + 0, 512); TC_RELINQ(); }
    if (tid == 0){ MBAR_INIT(MBAR); }
    __syncthreads();
    uint32_t tmem;
    asm volatile("ld.shared.b32 %0, [%1];" : "=r"(tmem) : "r"(sb + 0));

    uint32_t parity = 0;
    // ---- GEMM1: D_xk @ tmem+0 (240 cols), D_g @ tmem+256 (240 cols) ----
    for (int ch = 0; ch < NCHUNK; ch++){
        if (ch){ mbar_wait(MBAR, parity); parity ^= 1; }
        stageA(sb + FN_A, x, row0, ch, tid, THREADS);
        stageB(sb + FN_BX, Wx, ch, tid, THREADS);
        stageB(sb + FN_BG, Wg, ch, tid, THREADS);
        FENCE_ASYNC();
        __syncthreads();
        if (wid == 0 && elect_one()){
            uint64_t ad = sdesc(sb + FN_A), bx = sdesc(sb + FN_BX), bg = sdesc(sb + FN_BG);
            #pragma unroll
            for (int ks = 0; ks < 8; ks++){
                uint64_t ao   = (uint64_t)((ks >> 2)*1024 + (ks & 3)*2);
                uint64_t bofs = (uint64_t)((ks >> 2)*1920 + (ks & 3)*2);
                uint32_t en = (ch | ks) ? 1u : 0u;
                mma_tf32(tmem + 0,   ad + ao, bx + bofs, IDESC, en);
                mma_tf32(tmem + 256, ad + ao, bg + bofs, IDESC, en);
            }
            TC_COMMIT(MBAR);
        }
    }
    mbar_wait(MBAR, parity); parity ^= 1;
    TC_FENCE_AFTER();

    // ---- epilogue 1: y = xk * sigmoid(g) * diagT[s, c] -> smem tf32 tile ---
    if (wid < 4){
        int rl = wid*32 + lane;
        int row = row0 + rl;
        int s = row & (SEQ - 1);
        const float* dgr = g_diagT + (size_t)s*DIM;
        uint32_t woff = (uint32_t)wid << 21;
        for (int c0 = 0; c0 < 240; c0 += 32){
            uint32_t xr[32], gr[32];
            if (c0 < 224){
                LDTM32(xr, tmem + 0   + c0 + woff);
                LDTM32(gr, tmem + 256 + c0 + woff);
                TC_WAIT_LD();
                #pragma unroll
                for (int j = 0; j < 8; j++){
                    float4 dv = *(const float4*)(dgr + c0 + j*4);
                    float4 yv;
                    yv.x = __uint_as_float(xr[j*4+0]) * sigf(__uint_as_float(gr[j*4+0])) * dv.x;
                    yv.y = __uint_as_float(xr[j*4+1]) * sigf(__uint_as_float(gr[j*4+1])) * dv.y;
                    yv.z = __uint_as_float(xr[j*4+2]) * sigf(__uint_as_float(gr[j*4+2])) * dv.z;
                    yv.w = __uint_as_float(xr[j*4+3]) * sigf(__uint_as_float(gr[j*4+3])) * dv.w;
                    sts_tf32x4(sb + FN_Y + a_off(rl, c0 + j*4), yv);
                }
            } else {
                LDTM16(xr, tmem + 0   + c0 + woff);
                LDTM16(gr, tmem + 256 + c0 + woff);
                TC_WAIT_LD();
                #pragma unroll
                for (int j = 0; j < 4; j++){
                    float4 dv = *(const float4*)(dgr + c0 + j*4);
                    float4 yv;
                    yv.x = __uint_as_float(xr[j*4+0]) * sigf(__uint_as_float(gr[j*4+0])) * dv.x;
                    yv.y = __uint_as_float(xr[j*4+1]) * sigf(__uint_as_float(gr[j*4+1])) * dv.y;
                    yv.z = __uint_as_float(xr[j*4+2]) * sigf(__uint_as_float(gr[j*4+2])) * dv.z;
                    yv.w = __uint_as_float(xr[j*4+3]) * sigf(__uint_as_float(gr[j*4+3])) * dv.w;
                    sts_tf32x4(sb + FN_Y + a_off(rl, c0 + j*4), yv);
                }
            }
        }
        // zero-pad y cols 240..255
        #pragma unroll
        for (int j = 0; j < 4; j++){
            uint32_t addr = sb + FN_Y + a_off(rl, 240 + j*4);
            asm volatile("st.shared.v4.b32 [%0], {%1, %1, %1, %1};" :: "r"(addr), "r"(0u) : "memory");
        }
        TC_FENCE_BEFORE();
    } else {
        // warps 4-7: prefetch Wo chunk 0 concurrently
        stageB(sb + FN_WO, Wo, 0, tid - 128, 128);
    }
    FENCE_ASYNC();
    __syncthreads();
    TC_FENCE_AFTER();

    // ---- GEMM2: D_o @ tmem+0 (reuses D_xk cols; reads done above) ----
    for (int ch = 0; ch < NCHUNK; ch++){
        if (ch){
            mbar_wait(MBAR, parity); parity ^= 1;
            stageB(sb + FN_WO, Wo, ch, tid, THREADS);
            FENCE_ASYNC();
            __syncthreads();
        }
        if (wid == 0 && elect_one()){
            uint64_t yd = sdesc(sb + FN_Y), wd = sdesc(sb + FN_WO);
            #pragma unroll
            for (int ks = 0; ks < 8; ks++){
                uint64_t ao   = (uint64_t)((ch*2 + (ks >> 2))*1024 + (ks & 3)*2);
                uint64_t bofs = (uint64_t)((ks >> 2)*1920 + (ks & 3)*2);
                mma_tf32(tmem + 0, yd + ao, wd + bofs, IDESC, (ch | ks) ? 1u : 0u);
            }
            TC_COMMIT(MBAR);
        }
    }
    mbar_wait(MBAR, parity); parity ^= 1;
    TC_FENCE_AFTER();

    // ---- epilogue 2: + bias -> smem row-major -> coalesced STG ----
    if (wid < 4){
        int rl = wid*32 + lane;
        uint32_t woff = (uint32_t)wid << 21;
        for (int c0 = 0; c0 < 240; c0 += 32){
            uint32_t orr[32];
            if (c0 < 224){
                LDTM32(orr, tmem + c0 + woff);
                TC_WAIT_LD();
                #pragma unroll
                for (int j = 0; j < 8; j++){
                    float4 bv = *(const float4*)(bo + c0 + j*4);
                    float4 ov = make_float4(__uint_as_float(orr[j*4+0]) + bv.x,
                                            __uint_as_float(orr[j*4+1]) + bv.y,
                                            __uint_as_float(orr[j*4+2]) + bv.z,
                                            __uint_as_float(orr[j*4+3]) + bv.w);
                    *(float4*)(smem + FN_OUT + ((size_t)rl*DIM + c0 + j*4)*4) = ov;
                }
            } else {
                LDTM16(orr, tmem + c0 + woff);
                TC_WAIT_LD();
                #pragma unroll
                for (int j = 0; j < 4; j++){
                    float4 bv = *(const float4*)(bo + c0 + j*4);
                    float4 ov = make_float4(__uint_as_float(orr[j*4+0]) + bv.x,
                                            __uint_as_float(orr[j*4+1]) + bv.y,
                                            __uint_as_float(orr[j*4+2]) + bv.z,
                                            __uint_as_float(orr[j*4+3]) + bv.w);
                    *(float4*)(smem + FN_OUT + ((size_t)rl*DIM + c0 + j*4)*4) = ov;
                }
            }
        }
    }
    __syncthreads();
    {
        float4* go = (float4*)(out + (size_t)row0*DIM);
        const float4* so = (const float4*)(smem + FN_OUT);
        for (int i = tid; i < MTILE*DIM/4; i += THREADS) go[i] = so[i];
    }
    __syncthreads();
    if (wid == 0) TC_DEALLOC(tmem, 512);
#else
    // plain-fp32 fallback (compute_103 PTX pass; not executed on GB300)
    extern __shared__ char smem[];
    float* ys = (float*)(smem + 1024);        // [128][240]
    const int tid = threadIdx.x;
    const int row0 = blockIdx.x * MTILE;
    for (int idx = tid; idx < MTILE*DIM; idx += THREADS){
        int r = idx / DIM, c = idx % DIM;
        int row = row0 + r;
        const float* xr = x + (size_t)row*DIM;
        float xk = 0.f, gp = 0.f;
        for (int e = 0; e < DIM; e++){
            float xe = xr[e];
            xk += xe * Wx[(size_t)c*DIM + e];
            gp += xe * Wg[(size_t)c*DIM + e];
        }
        int s = row & (SEQ - 1);
        ys[(size_t)r*DIM + c] = xk * sigf(gp) * g_diagT[(size_t)s*DIM + c];
    }
    __syncthreads();
    for (int idx = tid; idx < MTILE*DIM; idx += THREADS){
        int r = idx / DIM, c = idx % DIM;
        float acc = bo[c];
        const float* yr = ys + (size_t)r*DIM;
        for (int d = 0; d < DIM; d++) acc += yr[d] * Wo[(size_t)c*DIM + d];
        out[((size_t)(row0 + r))*DIM + c] = acc;
    }
#endif
}

// ---------------- launch ----------------
extern "C" void kernel_launch(void* const* d_in, const int* in_sizes, int n_in,
                              void* d_out, int out_size){
    const float* x     = (const float*)d_in[0];
    const float* Wx    = (const float*)d_in[1];
    const float* Wk    = (const float*)d_in[2];
    const float* Wv    = (const float*)d_in[3];
    const float* Wg    = (const float*)d_in[4];
    const float* Wo    = (const float*)d_in[5];
    const float* bo    = (const float*)d_in[6];
    const float* dmask = (const float*)d_in[7];
    float* out = (float*)d_out;
    (void)in_sizes; (void)n_in; (void)out_size;

    cudaFuncSetAttribute(diag_tc,  cudaFuncAttributeMaxDynamicSharedMemorySize, DG_SMEM);
    cudaFuncSetAttribute(final_tc, cudaFuncAttributeMaxDynamicSharedMemorySize, FN_SMEM);

    compute_MT_kernel<<<dim3(16, 15), dim3(16, 16)>>>(Wk, Wv, dmask);
    cumsum_kernel<<<(NB*DIM + 255)/256, 256>>>(x);
    diag_tc<<<NROW/MTILE, THREADS, DG_SMEM>>>(x);
    final_tc<<<NROW/MTILE, THREADS, FN_SMEM>>>(x, Wx, Wg, Wo, bo, out);
}

// round 5
// speedup vs baseline: 4.3918x; 1.1048x over previous
#include <cuda_runtime.h>
#include <math.h>
#include <stdint.h>

#define DIM    240
#define SEQ    1024
#define NB     240
#define NROW   (NB*SEQ)      // 245760
#define MTILE  128
#define KC     32
#define NCHUNK 8
#define THREADS 256

// idesc: dtype=f32(1<<4), atype=tf32(2<<7), btype=tf32(2<<10), N=240(30<<17), M=128(8<<24)
#define IDESC ((1u<<4)|(2u<<7)|(2u<<10)|(30u<<17)|(8u<<24))

// tcgen05 is arch-SPECIFIC: only emit in the sm_103a/sm_100a cubin pass.
#if !defined(__CUDA_ARCH__) || defined(__CUDA_ARCH_FEAT_SM103_ALL) || defined(__CUDA_ARCH_FEAT_SM100_ALL) || defined(__CUDA_ARCH_FEAT_SM101_ALL)
#define HAS_TC 1
#else
#define HAS_TC 0
#endif

// ---------------- device scratch ----------------
__device__ float g_MT  [DIM*256];              // MT[f][e], e padded to 256 with zeros
__device__ float g_Xc  [(size_t)NROW*DIM];     // cumsum of x over s
__device__ float g_diagT[SEQ*DIM];             // diagT[s*240 + b]

// ---------------- helpers ----------------
__device__ __forceinline__ uint32_t smem_u32(const void* p){
    uint32_t a;
    asm("{ .reg .u64 t; cvta.to.shared.u64 t, %1; cvt.u32.u64 %0, t; }" : "=r"(a) : "l"(p));
    return a;
}
__device__ __forceinline__ float sigf(float v){
    float t = -1.4426950408889634f * v;
    float e; asm("ex2.approx.f32 %0, %1;" : "=f"(e) : "f"(t));
    float r; asm("rcp.approx.f32 %0, %1;" : "=f"(r) : "f"(1.f + e));
    return r;
}

#if HAS_TC
__device__ __forceinline__ uint32_t elect_one(){
    uint32_t p;
    asm volatile("{ .reg .pred p; elect.sync _|p, 0xFFFFFFFF; selp.b32 %0, 1, 0, p; }" : "=r"(p));
    return p;
}
__device__ __forceinline__ uint64_t sdesc(uint32_t addr){
    return ((uint64_t)2 << 61) | ((uint64_t)1 << 46) | ((uint64_t)64 << 32)
         | ((uint64_t)1 << 16) | ((uint64_t)(addr >> 4) & 0x3FFF);
}
__device__ __forceinline__ void mma_tf32(uint32_t d, uint64_t a, uint64_t b, uint32_t id, uint32_t en){
    asm volatile(
        "{\n\t.reg .pred p;\n\tsetp.ne.u32 p, %5, 0;\n\t"
        "tcgen05.mma.cta_group::1.kind::tf32 [%0], %1, %2, %3, {%4, %4, %4, %4}, p;\n\t}"
        :: "r"(d), "l"(a), "l"(b), "r"(id), "r"(0u), "r"(en) : "memory");
}
__device__ __forceinline__ void mbar_wait(uint32_t mbar, uint32_t phase){
    asm volatile(
        "{\n\t.reg .pred P;\n\t"
        "W%=:\n\t"
        "mbarrier.try_wait.parity.acquire.cta.shared::cta.b64 P, [%0], %1, 0x989680;\n\t"
        "@P bra.uni D%=;\n\t"
        "bra.uni W%=;\n\t"
        "D%=:\n\t}"
        :: "r"(mbar), "r"(phase) : "memory");
}
#define TC_ALLOC(sa, n)  asm volatile("tcgen05.alloc.cta_group::1.sync.aligned.shared::cta.b32 [%0], %1;" :: "r"(sa), "r"(n) : "memory")
#define TC_RELINQ()      asm volatile("tcgen05.relinquish_alloc_permit.cta_group::1.sync.aligned;")
#define TC_DEALLOC(t, n) asm volatile("tcgen05.dealloc.cta_group::1.sync.aligned.b32 %0, %1;" :: "r"(t), "r"(n))
#define TC_COMMIT(mb)    asm volatile("tcgen05.commit.cta_group::1.mbarrier::arrive::one.shared::cluster.b64 [%0];" :: "r"(mb) : "memory")
#define TC_WAIT_LD()     asm volatile("tcgen05.wait::ld.sync.aligned;" ::: "memory")
#define TC_FENCE_AFTER()  asm volatile("tcgen05.fence::after_thread_sync;" ::: "memory")
#define TC_FENCE_BEFORE() asm volatile("tcgen05.fence::before_thread_sync;" ::: "memory")
#define FENCE_ASYNC()    asm volatile("fence.proxy.async.shared::cta;" ::: "memory")
#define MBAR_INIT(a)     asm volatile("mbarrier.init.shared.b64 [%0], 1;" :: "r"(a) : "memory")

#define LDTM32(r, a) \
    asm volatile( \
        "tcgen05.ld.sync.aligned.32x32b.x32.b32 " \
        "{%0, %1, %2, %3, %4, %5, %6, %7, " \
        " %8, %9, %10, %11, %12, %13, %14, %15, " \
        " %16, %17, %18, %19, %20, %21, %22, %23, " \
        " %24, %25, %26, %27, %28, %29, %30, %31}, [%32];" \
        : "=r"((r)[0]),  "=r"((r)[1]),  "=r"((r)[2]),  "=r"((r)[3]), \
          "=r"((r)[4]),  "=r"((r)[5]),  "=r"((r)[6]),  "=r"((r)[7]), \
          "=r"((r)[8]),  "=r"((r)[9]),  "=r"((r)[10]), "=r"((r)[11]), \
          "=r"((r)[12]), "=r"((r)[13]), "=r"((r)[14]), "=r"((r)[15]), \
          "=r"((r)[16]), "=r"((r)[17]), "=r"((r)[18]), "=r"((r)[19]), \
          "=r"((r)[20]), "=r"((r)[21]), "=r"((r)[22]), "=r"((r)[23]), \
          "=r"((r)[24]), "=r"((r)[25]), "=r"((r)[26]), "=r"((r)[27]), \
          "=r"((r)[28]), "=r"((r)[29]), "=r"((r)[30]), "=r"((r)[31]) \
        : "r"(a))

#define LDTM16(r, a) \
    asm volatile( \
        "tcgen05.ld.sync.aligned.32x32b.x16.b32 " \
        "{%0, %1, %2, %3, %4, %5, %6, %7, " \
        " %8, %9, %10, %11, %12, %13, %14, %15}, [%16];" \
        : "=r"((r)[0]),  "=r"((r)[1]),  "=r"((r)[2]),  "=r"((r)[3]), \
          "=r"((r)[4]),  "=r"((r)[5]),  "=r"((r)[6]),  "=r"((r)[7]), \
          "=r"((r)[8]),  "=r"((r)[9]),  "=r"((r)[10]), "=r"((r)[11]), \
          "=r"((r)[12]), "=r"((r)[13]), "=r"((r)[14]), "=r"((r)[15]) \
        : "r"(a))

// ---------------- swizzled blocked-atom addressing (atom = 8 rows x 128B) ---
__device__ __forceinline__ uint32_t swz(uint32_t off){ return off ^ ((off >> 3) & 0x70); }
// 128-row tiles (A / Y): atom index = (k>>5)*16 + (r>>3)
__device__ __forceinline__ uint32_t a_off(int r, int k){
    uint32_t o = ((uint32_t)((k >> 5)*16 + (r >> 3)) << 10) + ((uint32_t)(r & 7) << 7) + ((uint32_t)(k & 31) << 2);
    return swz(o);
}
// 240-row tiles (B): atom index = (k>>5)*30 + (f>>3)
__device__ __forceinline__ uint32_t b_off(int f, int k){
    uint32_t o = ((uint32_t)((k >> 5)*30 + (f >> 3)) << 10) + ((uint32_t)(f & 7) << 7) + ((uint32_t)(k & 31) << 2);
    return swz(o);
}
__device__ __forceinline__ void sts_tf32x4(uint32_t addr, float4 v){
    uint32_t a, b, c, d;
    asm("cvt.rna.tf32.f32 %0, %1;" : "=r"(a) : "f"(v.x));
    asm("cvt.rna.tf32.f32 %0, %1;" : "=r"(b) : "f"(v.y));
    asm("cvt.rna.tf32.f32 %0, %1;" : "=r"(c) : "f"(v.z));
    asm("cvt.rna.tf32.f32 %0, %1;" : "=r"(d) : "f"(v.w));
    asm volatile("st.shared.v4.b32 [%0], {%1, %2, %3, %4};" :: "r"(addr), "r"(a), "r"(b), "r"(c), "r"(d) : "memory");
}

// ---------------- staging (KC=32 chunks) ----------------
__device__ __forceinline__ void stageA(uint32_t sa, const float* __restrict__ x,
                                       int row0, int ch, int tid){
    #pragma unroll
    for (int it = 0; it < 4; it++){
        int i = tid + it*THREADS;
        int r = i >> 3, q = i & 7;
        int gk = ch*KC + q*4;
        float4 v = make_float4(0.f, 0.f, 0.f, 0.f);
        if (gk < DIM) v = *(const float4*)(x + (size_t)(row0 + r)*DIM + gk);
        sts_tf32x4(sa + a_off(r, q*4), v);
    }
}
__device__ __forceinline__ void stageB(uint32_t sa, const float* __restrict__ W,
                                       int ch, int tid, int nthr){
    for (int i = tid; i < 240*8; i += nthr){
        int f = i >> 3, q = i & 7;
        int gk = ch*KC + q*4;
        float4 v = make_float4(0.f, 0.f, 0.f, 0.f);
        if (gk < DIM) v = *(const float4*)(W + (size_t)f*DIM + gk);
        sts_tf32x4(sa + b_off(f, q*4), v);
    }
}
__device__ __forceinline__ void stageB_MT(uint32_t sa, int ch, int tid){
    for (int i = tid; i < 240*8; i += THREADS){
        int f = i >> 3, q = i & 7;
        int gk = ch*KC + q*4;                 // MT padded to 256
        float4 v = *(const float4*)(g_MT + (size_t)f*256 + gk);
        sts_tf32x4(sa + b_off(f, q*4), v);
    }
}
#endif  // HAS_TC

// ---------------- prep kernels ----------------
__global__ void compute_MT_kernel(const float* __restrict__ Wk,
                                  const float* __restrict__ Wv,
                                  const float* __restrict__ dmask){
    __shared__ float As[16][17], Bs[16][17];
    int e = blockIdx.x*16 + threadIdx.x;   // 0..255
    float acc = 0.f;
    for (int d0 = 0; d0 < DIM; d0 += 16){
        As[threadIdx.y][threadIdx.x] = Wv[(d0 + threadIdx.y)*DIM + blockIdx.y*16 + threadIdx.x];
        Bs[threadIdx.y][threadIdx.x] = (e < DIM) ? Wk[(d0 + threadIdx.y)*DIM + e] : 0.f;
        __syncthreads();
        #pragma unroll
        for (int dd = 0; dd < 16; dd++)
            acc += As[dd][threadIdx.y] * Bs[dd][threadIdx.x];
        __syncthreads();
    }
    int f = blockIdx.y*16 + threadIdx.y;
    float decay = dmask[SEQ];              // decay_mask[1][0] == 0.9
    g_MT[(size_t)f*256 + e] = (e < DIM) ? acc * decay : 0.f;
}

__global__ void cumsum_kernel(const float* __restrict__ x){
    int idx = blockIdx.x*blockDim.x + threadIdx.x;
    if (idx >= NB*DIM) return;
    int b = idx / DIM, d = idx % DIM;
    const float* xp = x    + (size_t)b*SEQ*DIM + d;
    float*       cp = g_Xc + (size_t)b*SEQ*DIM + d;
    float acc = 0.f;
    for (int s = 0; s < SEQ; s += 8){
        float v[8];
        #pragma unroll
        for (int i = 0; i < 8; i++) v[i] = xp[(size_t)(s + i)*DIM];
        #pragma unroll
        for (int i = 0; i < 8; i++){ acc += v[i]; cp[(size_t)(s + i)*DIM] = acc; }
    }
}

// ---------------- K1: diag (pipelined) ----------------
#define DG_A0   1024u
#define DG_A1   17408u
#define DG_M0   33792u
#define DG_M1   64512u
#define DG_XC   95232u
#define DG_SMEM (DG_XC + 128u*244u*4u)   // 220160

__global__ void __launch_bounds__(THREADS, 1) __cluster_dims__(1, 1, 1)
diag_tc(const float* __restrict__ x){
#if HAS_TC
    extern __shared__ char smem[];
    uint32_t sb = smem_u32(smem);
    const int tid = threadIdx.x;
    const int wid = tid >> 5, lane = tid & 31;
    const int row0 = blockIdx.x * MTILE;
    uint32_t mbar[2] = { sb + 8, sb + 16 };
    uint32_t ph[2]   = { 0, 0 };
    const uint32_t abuf[2] = { sb + DG_A0, sb + DG_A1 };
    const uint32_t mbuf[2] = { sb + DG_M0, sb + DG_M1 };

    if (wid == 0){ TC_ALLOC(sb + 0, 512); TC_RELINQ(); }
    if (tid == 0){ MBAR_INIT(mbar[0]); MBAR_INIT(mbar[1]); }
    __syncthreads();
    uint32_t tmem;
    asm volatile("ld.shared.b32 %0, [%1];" : "=r"(tmem) : "r"(sb + 0));

    // stage Xc tile [128][244]
    float* xcs = (float*)(smem + DG_XC);
    for (int i = tid; i < MTILE*60; i += THREADS){
        int r = i / 60, q = i % 60;
        float4 v = *(const float4*)(g_Xc + (size_t)(row0 + r)*DIM + q*4);
        *(float4*)(xcs + r*244 + q*4) = v;
    }

    for (int ch = 0; ch < NCHUNK; ch++){
        int p = ch & 1;
        if (ch >= 2){ mbar_wait(mbar[p], ph[p]); ph[p] ^= 1; }
        stageA(abuf[p], x, row0, ch, tid);
        stageB_MT(mbuf[p], ch, tid);
        FENCE_ASYNC();
        __syncthreads();
        if (wid == 0 && elect_one()){
            uint64_t ad = sdesc(abuf[p]), bd = sdesc(mbuf[p]);
            int nks = (ch == NCHUNK-1) ? 2 : 4;
            for (int ks = 0; ks < nks; ks++){
                mma_tf32(tmem, ad + ks*2, bd + ks*2, IDESC, (ch | ks) ? 1u : 0u);
            }
            TC_COMMIT(mbar[p]);
        }
    }
    mbar_wait(mbar[0], ph[0]); ph[0] ^= 1;
    mbar_wait(mbar[1], ph[1]); ph[1] ^= 1;
    TC_FENCE_AFTER();

    if (wid < 4){
        int rl = wid*32 + lane;
        int row = row0 + rl;
        uint32_t woff = (uint32_t)wid << 21;
        float acc = 0.f;
        for (int c0 = 0; c0 < 240; c0 += 32){
            uint32_t pr[32];
            if (c0 < 224){
                LDTM32(pr, tmem + c0 + woff);
                TC_WAIT_LD();
                #pragma unroll
                for (int j = 0; j < 8; j++){
                    float4 c4 = *(const float4*)(xcs + rl*244 + c0 + j*4);
                    acc += __uint_as_float(pr[j*4+0])*c4.x + __uint_as_float(pr[j*4+1])*c4.y
                         + __uint_as_float(pr[j*4+2])*c4.z + __uint_as_float(pr[j*4+3])*c4.w;
                }
            } else {
                LDTM16(pr, tmem + c0 + woff);
                TC_WAIT_LD();
                #pragma unroll
                for (int j = 0; j < 4; j++){
                    float4 c4 = *(const float4*)(xcs + rl*244 + c0 + j*4);
                    acc += __uint_as_float(pr[j*4+0])*c4.x + __uint_as_float(pr[j*4+1])*c4.y
                         + __uint_as_float(pr[j*4+2])*c4.z + __uint_as_float(pr[j*4+3])*c4.w;
                }
            }
        }
        int b = row >> 10, s = row & (SEQ - 1);
        g_diagT[(size_t)s*DIM + b] = acc;
    }
    __syncthreads();
    if (wid == 0) TC_DEALLOC(tmem, 512);
#else
    const int tid = threadIdx.x;
    const int row0 = blockIdx.x * MTILE;
    __shared__ float red[THREADS];
    int r = tid >> 1, half = tid & 1;
    int row = row0 + r;
    float acc = 0.f;
    for (int f = half*120; f < half*120 + 120; f++){
        float p = 0.f;
        for (int e = 0; e < DIM; e++) p += x[(size_t)row*DIM + e] * g_MT[(size_t)f*256 + e];
        acc += p * g_Xc[(size_t)row*DIM + f];
    }
    red[tid] = acc;
    __syncthreads();
    if (half == 0){
        int b = row >> 10, s = row & (SEQ - 1);
        g_diagT[(size_t)s*DIM + b] = red[tid] + red[tid + 1];
    }
#endif
}

// ---------------- K2: fused final (pipelined) ----------------
#define FN_A0   1024u
#define FN_A1   17408u
#define FN_BX0  33792u
#define FN_BX1  64512u
#define FN_BG0  95232u
#define FN_BG1  125952u      // end 156672
#define FN_Y    1024u        // 131072, over GEMM1 buffers (dead)
#define FN_WO0  132096u
#define FN_WO1  162816u      // end 193536
#define FN_OUT  1024u        // over Y (dead after GEMM2)
#define FN_SMEM 193536u

__global__ void __launch_bounds__(THREADS, 1) __cluster_dims__(1, 1, 1)
final_tc(const float* __restrict__ x,  const float* __restrict__ Wx,
         const float* __restrict__ Wg, const float* __restrict__ Wo,
         const float* __restrict__ bo, float* __restrict__ out){
#if HAS_TC
    extern __shared__ char smem[];
    uint32_t sb = smem_u32(smem);
    const int tid = threadIdx.x;
    const int wid = tid >> 5, lane = tid & 31;
    const int row0 = blockIdx.x * MTILE;
    // Disjoint barrier pairs: {0,1} for GEMM1, {2,3} for GEMM2 — no phase
    // coupling across sections (R4 deadlock root cause).
    uint32_t mbar[4] = { sb + 8, sb + 16, sb + 24, sb + 32 };
    uint32_t ph[4]   = { 0, 0, 0, 0 };
    const uint32_t abuf[2] = { sb + FN_A0,  sb + FN_A1  };
    const uint32_t xbuf[2] = { sb + FN_BX0, sb + FN_BX1 };
    const uint32_t gbuf[2] = { sb + FN_BG0, sb + FN_BG1 };
    const uint32_t obuf[2] = { sb + FN_WO0, sb + FN_WO1 };

    if (wid == 0){ TC_ALLOC(sb + 0, 512); TC_RELINQ(); }
    if (tid == 0){ MBAR_INIT(mbar[0]); MBAR_INIT(mbar[1]); MBAR_INIT(mbar[2]); MBAR_INIT(mbar[3]); }
    __syncthreads();
    uint32_t tmem;
    asm volatile("ld.shared.b32 %0, [%1];" : "=r"(tmem) : "r"(sb + 0));

    // ---- GEMM1 (pipelined): D_xk @ tmem+0, D_g @ tmem+256 ----
    for (int ch = 0; ch < NCHUNK; ch++){
        int p = ch & 1;
        if (ch >= 2){ mbar_wait(mbar[p], ph[p]); ph[p] ^= 1; }
        stageA(abuf[p], x, row0, ch, tid);
        stageB(xbuf[p], Wx, ch, tid, THREADS);
        stageB(gbuf[p], Wg, ch, tid, THREADS);
        FENCE_ASYNC();
        __syncthreads();
        if (wid == 0 && elect_one()){
            uint64_t ad = sdesc(abuf[p]), bx = sdesc(xbuf[p]), bg = sdesc(gbuf[p]);
            int nks = (ch == NCHUNK-1) ? 2 : 4;
            for (int ks = 0; ks < nks; ks++){
                uint32_t en = (ch | ks) ? 1u : 0u;
                mma_tf32(tmem + 0,   ad + ks*2, bx + ks*2, IDESC, en);
                mma_tf32(tmem + 256, ad + ks*2, bg + ks*2, IDESC, en);
            }
            TC_COMMIT(mbar[p]);
        }
    }
    mbar_wait(mbar[0], ph[0]); ph[0] ^= 1;
    mbar_wait(mbar[1], ph[1]); ph[1] ^= 1;
    TC_FENCE_AFTER();

    // ---- epilogue 1: y = xk * sigmoid(g) * diagT[s, c] -> smem Y tile ----
    // warps 4-7 concurrently prefetch Wo chunks 0 and 1
    if (wid < 4){
        int rl = wid*32 + lane;
        int row = row0 + rl;
        int s = row & (SEQ - 1);
        const float* dgr = g_diagT + (size_t)s*DIM;
        uint32_t woff = (uint32_t)wid << 21;
        for (int c0 = 0; c0 < 240; c0 += 32){
            uint32_t xr[32], gr[32];
            if (c0 < 224){
                LDTM32(xr, tmem + 0   + c0 + woff);
                LDTM32(gr, tmem + 256 + c0 + woff);
                TC_WAIT_LD();
                #pragma unroll
                for (int j = 0; j < 8; j++){
                    float4 dv = *(const float4*)(dgr + c0 + j*4);
                    float4 yv;
                    yv.x = __uint_as_float(xr[j*4+0]) * sigf(__uint_as_float(gr[j*4+0])) * dv.x;
                    yv.y = __uint_as_float(xr[j*4+1]) * sigf(__uint_as_float(gr[j*4+1])) * dv.y;
                    yv.z = __uint_as_float(xr[j*4+2]) * sigf(__uint_as_float(gr[j*4+2])) * dv.z;
                    yv.w = __uint_as_float(xr[j*4+3]) * sigf(__uint_as_float(gr[j*4+3])) * dv.w;
                    sts_tf32x4(sb + FN_Y + a_off(rl, c0 + j*4), yv);
                }
            } else {
                LDTM16(xr, tmem + 0   + c0 + woff);
                LDTM16(gr, tmem + 256 + c0 + woff);
                TC_WAIT_LD();
                #pragma unroll
                for (int j = 0; j < 4; j++){
                    float4 dv = *(const float4*)(dgr + c0 + j*4);
                    float4 yv;
                    yv.x = __uint_as_float(xr[j*4+0]) * sigf(__uint_as_float(gr[j*4+0])) * dv.x;
                    yv.y = __uint_as_float(xr[j*4+1]) * sigf(__uint_as_float(gr[j*4+1])) * dv.y;
                    yv.z = __uint_as_float(xr[j*4+2]) * sigf(__uint_as_float(gr[j*4+2])) * dv.z;
                    yv.w = __uint_as_float(xr[j*4+3]) * sigf(__uint_as_float(gr[j*4+3])) * dv.w;
                    sts_tf32x4(sb + FN_Y + a_off(rl, c0 + j*4), yv);
                }
            }
        }
        TC_FENCE_BEFORE();   // TMEM reads done before GEMM2 overwrites tmem+0
    } else {
        // prefetch Wo chunks 0 and 1 with 128 threads
        int t2 = tid - 128;
        stageB(obuf[0], Wo, 0, t2, 128);
        stageB(obuf[1], Wo, 1, t2, 128);
    }
    FENCE_ASYNC();
    __syncthreads();
    TC_FENCE_AFTER();

    // ---- GEMM2 (pipelined): D_o @ tmem+0, A = Y smem, B = Wo chunks ----
    for (int ch = 0; ch < NCHUNK; ch++){
        int p = ch & 1;
        if (ch >= 2){
            mbar_wait(mbar[2 + p], ph[2 + p]); ph[2 + p] ^= 1;
            stageB(obuf[p], Wo, ch, tid, THREADS);
            FENCE_ASYNC();
            __syncthreads();
        }
        if (wid == 0 && elect_one()){
            uint64_t yd = sdesc(sb + FN_Y), wd = sdesc(obuf[p]);
            int nks = (ch == NCHUNK-1) ? 2 : 4;
            for (int ks = 0; ks < nks; ks++){
                int gks = ch*4 + ks;  // global k-step 0..29
                uint64_t ao = (uint64_t)((gks >> 2)*1024 + (gks & 3)*2);
                mma_tf32(tmem + 0, yd + ao, wd + ks*2, IDESC, (ch | ks) ? 1u : 0u);
            }
            TC_COMMIT(mbar[2 + p]);
        }
    }
    mbar_wait(mbar[2], ph[2]); ph[2] ^= 1;
    mbar_wait(mbar[3], ph[3]); ph[3] ^= 1;
    TC_FENCE_AFTER();

    // ---- epilogue 2: + bias -> smem row-major -> coalesced STG ----
    if (wid < 4){
        int rl = wid*32 + lane;
        uint32_t woff = (uint32_t)wid << 21;
        for (int c0 = 0; c0 < 240; c0 += 32){
            uint32_t orr[32];
            if (c0 < 224){
                LDTM32(orr, tmem + c0 + woff);
                TC_WAIT_LD();
                #pragma unroll
                for (int j = 0; j < 8; j++){
                    float4 bv = *(const float4*)(bo + c0 + j*4);
                    float4 ov = make_float4(__uint_as_float(orr[j*4+0]) + bv.x,
                                            __uint_as_float(orr[j*4+1]) + bv.y,
                                            __uint_as_float(orr[j*4+2]) + bv.z,
                                            __uint_as_float(orr[j*4+3]) + bv.w);
                    *(float4*)(smem + FN_OUT + ((size_t)rl*DIM + c0 + j*4)*4) = ov;
                }
            } else {
                LDTM16(orr, tmem + c0 + woff);
                TC_WAIT_LD();
                #pragma unroll
                for (int j = 0; j < 4; j++){
                    float4 bv = *(const float4*)(bo + c0 + j*4);
                    float4 ov = make_float4(__uint_as_float(orr[j*4+0]) + bv.x,
                                            __uint_as_float(orr[j*4+1]) + bv.y,
                                            __uint_as_float(orr[j*4+2]) + bv.z,
                                            __uint_as_float(orr[j*4+3]) + bv.w);
                    *(float4*)(smem + FN_OUT + ((size_t)rl*DIM + c0 + j*4)*4) = ov;
                }
            }
        }
    }
    __syncthreads();
    {
        float4* go = (float4*)(out + (size_t)row0*DIM);
        const float4* so = (const float4*)(smem + FN_OUT);
        for (int i = tid; i < MTILE*DIM/4; i += THREADS) go[i] = so[i];
    }
    __syncthreads();
    if (wid == 0) TC_DEALLOC(tmem, 512);
#else
    extern __shared__ char smem[];
    float* ys = (float*)(smem + 1024);
    const int tid = threadIdx.x;
    const int row0 = blockIdx.x * MTILE;
    for (int idx = tid; idx < MTILE*DIM; idx += THREADS){
        int r = idx / DIM, c = idx % DIM;
        int row = row0 + r;
        const float* xr = x + (size_t)row*DIM;
        float xk = 0.f, gp = 0.f;
        for (int e = 0; e < DIM; e++){
            float xe = xr[e];
            xk += xe * Wx[(size_t)c*DIM + e];
            gp += xe * Wg[(size_t)c*DIM + e];
        }
        int s = row & (SEQ - 1);
        ys[(size_t)r*DIM + c] = xk * sigf(gp) * g_diagT[(size_t)s*DIM + c];
    }
    __syncthreads();
    for (int idx = tid; idx < MTILE*DIM; idx += THREADS){
        int r = idx / DIM, c = idx % DIM;
        float acc = bo[c];
        const float* yr = ys + (size_t)r*DIM;
        for (int d = 0; d < DIM; d++) acc += yr[d] * Wo[(size_t)c*DIM + d];
        out[((size_t)(row0 + r))*DIM + c] = acc;
    }
#endif
}

// ---------------- launch ----------------
extern "C" void kernel_launch(void* const* d_in, const int* in_sizes, int n_in,
                              void* d_out, int out_size){
    const float* x     = (const float*)d_in[0];
    const float* Wx    = (const float*)d_in[1];
    const float* Wk    = (const float*)d_in[2];
    const float* Wv    = (const float*)d_in[3];
    const float* Wg    = (const float*)d_in[4];
    const float* Wo    = (const float*)d_in[5];
    const float* bo    = (const float*)d_in[6];
    const float* dmask = (const float*)d_in[7];
    float* out = (float*)d_out;
    (void)in_sizes; (void)n_in; (void)out_size;

    cudaFuncSetAttribute(diag_tc,  cudaFuncAttributeMaxDynamicSharedMemorySize, DG_SMEM);
    cudaFuncSetAttribute(final_tc, cudaFuncAttributeMaxDynamicSharedMemorySize, FN_SMEM);

    compute_MT_kernel<<<dim3(16, 15), dim3(16, 16)>>>(Wk, Wv, dmask);
    cumsum_kernel<<<(NB*DIM + 255)/256, 256>>>(x);
    diag_tc<<<NROW/MTILE, THREADS, DG_SMEM>>>(x);
    final_tc<<<NROW/MTILE, THREADS, FN_SMEM>>>(x, Wx, Wg, Wo, bo, out);
}

// round 6
// speedup vs baseline: 6.0943x; 1.3877x over previous
#include <cuda_runtime.h>
#include <math.h>
#include <stdint.h>

#define DIM    240
#define SEQ    1024
#define NB     240
#define NROW   (NB*SEQ)      // 245760
#define MTILE  128
#define KC     32
#define NCHUNK 8
#define THREADS 256

#define A_CH_BYTES  16384u   // 128 rows x 128B
#define B_CH_BYTES  30720u   // 240 rows x 128B
#define XC_BYTES    122880u  // 128 x 240 x 4

// idesc: dtype=f32(1<<4), atype=tf32(2<<7), btype=tf32(2<<10), N=240(30<<17), M=128(8<<24)
#define IDESC ((1u<<4)|(2u<<7)|(2u<<10)|(30u<<17)|(8u<<24))

#if !defined(__CUDA_ARCH__) || defined(__CUDA_ARCH_FEAT_SM103_ALL) || defined(__CUDA_ARCH_FEAT_SM100_ALL) || defined(__CUDA_ARCH_FEAT_SM101_ALL)
#define HAS_TC 1
#else
#define HAS_TC 0
#endif

// ---------------- device scratch ----------------
__device__ __align__(1024) float g_Wsw[3][NCHUNK*7680];   // Wx,Wg,Wo swizzled tf32 chunks
__device__ __align__(1024) float g_MTsw[NCHUNK*7680];     // MT swizzled tf32 chunks
__device__ __align__(1024) float g_xsw[(size_t)NROW*256]; // x tiles swizzled tf32 [tile][ch][4096]
__device__ __align__(1024) float g_Xc [(size_t)NROW*DIM]; // cumsum of x over s
__device__ __align__(1024) float g_diagT[SEQ*DIM];        // diagT[s*240 + b]

// ---------------- helpers ----------------
__device__ __forceinline__ uint32_t smem_u32(const void* p){
    uint32_t a;
    asm("{ .reg .u64 t; cvta.to.shared.u64 t, %1; cvt.u32.u64 %0, t; }" : "=r"(a) : "l"(p));
    return a;
}
__device__ __forceinline__ float sigf(float v){
    float t = -1.4426950408889634f * v;
    float e; asm("ex2.approx.f32 %0, %1;" : "=f"(e) : "f"(t));
    float r; asm("rcp.approx.f32 %0, %1;" : "=f"(r) : "f"(1.f + e));
    return r;
}
__device__ __forceinline__ uint32_t cvt_tf32(float v){
    uint32_t r; asm("cvt.rna.tf32.f32 %0, %1;" : "=r"(r) : "f"(v)); return r;
}
// swizzle + per-chunk local offsets (atom = 8 rows x 128B, SW128)
__device__ __forceinline__ uint32_t swz(uint32_t off){ return off ^ ((off >> 3) & 0x70); }
__device__ __forceinline__ uint32_t loc_off(int r, int kl){   // r = row in tile, kl = k in [0,32)
    return swz(((uint32_t)(r >> 3) << 10) + ((uint32_t)(r & 7) << 7) + ((uint32_t)kl << 2));
}

#if HAS_TC
__device__ __forceinline__ uint32_t elect_one(){
    uint32_t p;
    asm volatile("{ .reg .pred p; elect.sync _|p, 0xFFFFFFFF; selp.b32 %0, 1, 0, p; }" : "=r"(p));
    return p;
}
__device__ __forceinline__ uint64_t sdesc(uint32_t addr){
    return ((uint64_t)2 << 61) | ((uint64_t)1 << 46) | ((uint64_t)64 << 32)
         | ((uint64_t)1 << 16) | ((uint64_t)(addr >> 4) & 0x3FFF);
}
__device__ __forceinline__ void mma_tf32(uint32_t d, uint64_t a, uint64_t b, uint32_t id, uint32_t en){
    asm volatile(
        "{\n\t.reg .pred p;\n\tsetp.ne.u32 p, %5, 0;\n\t"
        "tcgen05.mma.cta_group::1.kind::tf32 [%0], %1, %2, %3, {%4, %4, %4, %4}, p;\n\t}"
        :: "r"(d), "l"(a), "l"(b), "r"(id), "r"(0u), "r"(en) : "memory");
}
__device__ __forceinline__ void mbar_wait(uint32_t mbar, uint32_t phase){
    asm volatile(
        "{\n\t.reg .pred P;\n\t"
        "W%=:\n\t"
        "mbarrier.try_wait.parity.acquire.cta.shared::cta.b64 P, [%0], %1, 0x989680;\n\t"
        "@P bra.uni D%=;\n\t"
        "bra.uni W%=;\n\t"
        "D%=:\n\t}"
        :: "r"(mbar), "r"(phase) : "memory");
}
#define TC_ALLOC(sa, n)  asm volatile("tcgen05.alloc.cta_group::1.sync.aligned.shared::cta.b32 [%0], %1;" :: "r"(sa), "r"(n) : "memory")
#define TC_RELINQ()      asm volatile("tcgen05.relinquish_alloc_permit.cta_group::1.sync.aligned;")
#define TC_DEALLOC(t, n) asm volatile("tcgen05.dealloc.cta_group::1.sync.aligned.b32 %0, %1;" :: "r"(t), "r"(n))
#define TC_COMMIT(mb)    asm volatile("tcgen05.commit.cta_group::1.mbarrier::arrive::one.shared::cluster.b64 [%0];" :: "r"(mb) : "memory")
#define TC_WAIT_LD()     asm volatile("tcgen05.wait::ld.sync.aligned;" ::: "memory")
#define TC_FENCE_AFTER()  asm volatile("tcgen05.fence::after_thread_sync;" ::: "memory")
#define TC_FENCE_BEFORE() asm volatile("tcgen05.fence::before_thread_sync;" ::: "memory")
#define FENCE_ASYNC()    asm volatile("fence.proxy.async.shared::cta;" ::: "memory")
#define MBAR_INIT(a)     asm volatile("mbarrier.init.shared.b64 [%0], 1;" :: "r"(a) : "memory")
#define MBAR_EXPECT(a,n) asm volatile("mbarrier.arrive.expect_tx.shared.b64 _, [%0], %1;" :: "r"(a), "r"(n) : "memory")
#define BULK_G2S(sa, gp, n, mb) \
    asm volatile("cp.async.bulk.shared::cta.global.mbarrier::complete_tx::bytes [%0], [%1], %2, [%3];" \
        :: "r"(sa), "l"(gp), "r"(n), "r"(mb) : "memory")
#define BULK_S2G(gp, sa, n) \
    asm volatile("cp.async.bulk.global.shared::cta.bulk_group [%0], [%1], %2;" \
        :: "l"(gp), "r"(sa), "r"(n) : "memory")
#define BULK_COMMIT() asm volatile("cp.async.bulk.commit_group;" ::: "memory")
#define BULK_WAIT0()  asm volatile("cp.async.bulk.wait_group 0;" ::: "memory")

#define LDTM32(r, a) \
    asm volatile( \
        "tcgen05.ld.sync.aligned.32x32b.x32.b32 " \
        "{%0, %1, %2, %3, %4, %5, %6, %7, " \
        " %8, %9, %10, %11, %12, %13, %14, %15, " \
        " %16, %17, %18, %19, %20, %21, %22, %23, " \
        " %24, %25, %26, %27, %28, %29, %30, %31}, [%32];" \
        : "=r"((r)[0]),  "=r"((r)[1]),  "=r"((r)[2]),  "=r"((r)[3]), \
          "=r"((r)[4]),  "=r"((r)[5]),  "=r"((r)[6]),  "=r"((r)[7]), \
          "=r"((r)[8]),  "=r"((r)[9]),  "=r"((r)[10]), "=r"((r)[11]), \
          "=r"((r)[12]), "=r"((r)[13]), "=r"((r)[14]), "=r"((r)[15]), \
          "=r"((r)[16]), "=r"((r)[17]), "=r"((r)[18]), "=r"((r)[19]), \
          "=r"((r)[20]), "=r"((r)[21]), "=r"((r)[22]), "=r"((r)[23]), \
          "=r"((r)[24]), "=r"((r)[25]), "=r"((r)[26]), "=r"((r)[27]), \
          "=r"((r)[28]), "=r"((r)[29]), "=r"((r)[30]), "=r"((r)[31]) \
        : "r"(a))

#define LDTM16(r, a) \
    asm volatile( \
        "tcgen05.ld.sync.aligned.32x32b.x16.b32 " \
        "{%0, %1, %2, %3, %4, %5, %6, %7, " \
        " %8, %9, %10, %11, %12, %13, %14, %15}, [%16];" \
        : "=r"((r)[0]),  "=r"((r)[1]),  "=r"((r)[2]),  "=r"((r)[3]), \
          "=r"((r)[4]),  "=r"((r)[5]),  "=r"((r)[6]),  "=r"((r)[7]), \
          "=r"((r)[8]),  "=r"((r)[9]),  "=r"((r)[10]), "=r"((r)[11]), \
          "=r"((r)[12]), "=r"((r)[13]), "=r"((r)[14]), "=r"((r)[15]) \
        : "r"(a))

__device__ __forceinline__ void sts_tf32x4(uint32_t addr, float4 v){
    uint32_t a = cvt_tf32(v.x), b = cvt_tf32(v.y), c = cvt_tf32(v.z), d = cvt_tf32(v.w);
    asm volatile("st.shared.v4.b32 [%0], {%1, %2, %3, %4};" :: "r"(addr), "r"(a), "r"(b), "r"(c), "r"(d) : "memory");
}
#endif  // HAS_TC

// ---------------- prep kernels ----------------
// weights -> tf32, swizzled per-chunk images
__global__ void weights_swz_kernel(const float* __restrict__ Wx,
                                   const float* __restrict__ Wg,
                                   const float* __restrict__ Wo){
    int i = blockIdx.x*blockDim.x + threadIdx.x;     // over 240*240
    if (i >= DIM*DIM) return;
    int f = i / DIM, k = i % DIM;
    const float* W = (blockIdx.y == 0) ? Wx : (blockIdx.y == 1) ? Wg : Wo;
    uint32_t v = cvt_tf32(W[i]);
    int ch = k >> 5;
    char* dst = (char*)&g_Wsw[blockIdx.y][0] + (size_t)ch*B_CH_BYTES + loc_off(f, k & 31);
    *(uint32_t*)dst = v;
}

// MT[f][e] = decay * sum_d Wv[d,f]*Wk[d,e], written swizzled tf32
__global__ void compute_MT_kernel(const float* __restrict__ Wk,
                                  const float* __restrict__ Wv,
                                  const float* __restrict__ dmask){
    __shared__ float As[16][17], Bs[16][17];
    int e = blockIdx.x*16 + threadIdx.x;   // 0..239
    float acc = 0.f;
    for (int d0 = 0; d0 < DIM; d0 += 16){
        As[threadIdx.y][threadIdx.x] = Wv[(d0 + threadIdx.y)*DIM + blockIdx.y*16 + threadIdx.x];
        Bs[threadIdx.y][threadIdx.x] = Wk[(d0 + threadIdx.y)*DIM + e];
        __syncthreads();
        #pragma unroll
        for (int dd = 0; dd < 16; dd++)
            acc += As[dd][threadIdx.y] * Bs[dd][threadIdx.x];
        __syncthreads();
    }
    int f = blockIdx.y*16 + threadIdx.y;
    float decay = dmask[SEQ];              // decay_mask[1][0] == 0.9
    uint32_t v = cvt_tf32(acc * decay);
    int ch = e >> 5;
    char* dst = (char*)g_MTsw + (size_t)ch*B_CH_BYTES + loc_off(f, e & 31);
    *(uint32_t*)dst = v;
}

// x -> tf32, swizzled per (tile, chunk) 16KB images
__global__ void xsw_kernel(const float* __restrict__ x){
    int i = blockIdx.x*blockDim.x + threadIdx.x;     // over NROW*60 granules
    if (i >= NROW*60) return;
    int r = i / 60, q = i % 60;
    int k = q*4, ch = k >> 5, kl = k & 31;
    float4 v = *(const float4*)(x + (size_t)r*DIM + k);
    uint4 o = make_uint4(cvt_tf32(v.x), cvt_tf32(v.y), cvt_tf32(v.z), cvt_tf32(v.w));
    char* dst = (char*)g_xsw + ((size_t)(r >> 7)*NCHUNK + ch)*A_CH_BYTES + loc_off(r & 127, kl);
    *(uint4*)dst = o;
}

// inclusive cumsum of x over s per (b,d)
__global__ void cumsum_kernel(const float* __restrict__ x){
    int idx = blockIdx.x*blockDim.x + threadIdx.x;
    if (idx >= NB*DIM) return;
    int b = idx / DIM, d = idx % DIM;
    const float* xp = x    + (size_t)b*SEQ*DIM + d;
    float*       cp = g_Xc + (size_t)b*SEQ*DIM + d;
    float acc = 0.f;
    for (int s = 0; s < SEQ; s += 8){
        float v[8];
        #pragma unroll
        for (int i = 0; i < 8; i++) v[i] = xp[(size_t)(s + i)*DIM];
        #pragma unroll
        for (int i = 0; i < 8; i++){ acc += v[i]; cp[(size_t)(s + i)*DIM] = acc; }
    }
}

// ---------------- K1: diag ----------------
#define DG_A0   1024u
#define DG_A1   17408u
#define DG_M0   33792u
#define DG_M1   64512u
#define DG_XC   95232u
#define DG_SMEM 218112u

__global__ void __launch_bounds__(THREADS, 1) __cluster_dims__(1, 1, 1)
diag_tc(const float* __restrict__ x){
#if HAS_TC
    extern __shared__ char smem[];
    uint32_t sb = smem_u32(smem);
    const int tid = threadIdx.x;
    const int wid = tid >> 5, lane = tid & 31;
    const int row0 = blockIdx.x * MTILE;
    const uint32_t FUL0 = sb + 8,  FUL1 = sb + 16;
    const uint32_t FRE0 = sb + 24, FRE1 = sb + 32;
    const uint32_t XCB  = sb + 40;
    const uint32_t abuf[2] = { sb + DG_A0, sb + DG_A1 };
    const uint32_t mbuf[2] = { sb + DG_M0, sb + DG_M1 };

    if (wid == 0){ TC_ALLOC(sb + 0, 512); TC_RELINQ(); }
    if (tid == 0){ MBAR_INIT(FUL0); MBAR_INIT(FUL1); MBAR_INIT(FRE0); MBAR_INIT(FRE1); MBAR_INIT(XCB); }
    __syncthreads();
    uint32_t tmem;
    asm volatile("ld.shared.b32 %0, [%1];" : "=r"(tmem) : "r"(sb + 0));

    int isE = 0;
    if (wid == 0) isE = elect_one();

    if (isE){
        const uint64_t xg  = __cvta_generic_to_global(g_xsw) + (size_t)blockIdx.x*NCHUNK*A_CH_BYTES;
        const uint64_t mg  = __cvta_generic_to_global(g_MTsw);
        const uint64_t xcg = __cvta_generic_to_global(g_Xc) + (size_t)row0*DIM*4;
        MBAR_EXPECT(XCB, XC_BYTES);
        BULK_G2S(sb + DG_XC, xcg, XC_BYTES, XCB);
        MBAR_EXPECT(FUL0, A_CH_BYTES + B_CH_BYTES);
        BULK_G2S(abuf[0], xg,               A_CH_BYTES, FUL0);
        BULK_G2S(mbuf[0], mg,               B_CH_BYTES, FUL0);
        MBAR_EXPECT(FUL1, A_CH_BYTES + B_CH_BYTES);
        BULK_G2S(abuf[1], xg + A_CH_BYTES,  A_CH_BYTES, FUL1);
        BULK_G2S(mbuf[1], mg + B_CH_BYTES,  B_CH_BYTES, FUL1);

        uint32_t pf0 = 0, pf1 = 0, pr0 = 0, pr1 = 0;
        #pragma unroll
        for (int ch = 0; ch < NCHUNK; ch++){
            int p = ch & 1;
            uint32_t FUL = p ? FUL1 : FUL0, FRE = p ? FRE1 : FRE0;
            if (ch >= 2){
                if (p){ mbar_wait(FRE, pr1); pr1 ^= 1; } else { mbar_wait(FRE, pr0); pr0 ^= 1; }
                MBAR_EXPECT(FUL, A_CH_BYTES + B_CH_BYTES);
                BULK_G2S(abuf[p], xg + (size_t)ch*A_CH_BYTES, A_CH_BYTES, FUL);
                BULK_G2S(mbuf[p], mg + (size_t)ch*B_CH_BYTES, B_CH_BYTES, FUL);
            }
            if (p){ mbar_wait(FUL, pf1); pf1 ^= 1; } else { mbar_wait(FUL, pf0); pf0 ^= 1; }
            uint64_t ad = sdesc(abuf[p]), bd = sdesc(mbuf[p]);
            int nks = (ch == NCHUNK-1) ? 2 : 4;
            for (int ks = 0; ks < nks; ks++)
                mma_tf32(tmem, ad + ks*2, bd + ks*2, IDESC, (ch | ks) ? 1u : 0u);
            TC_COMMIT(FRE);
        }
        mbar_wait(FRE0, pr0);
        mbar_wait(FRE1, pr1);
    }
    __syncthreads();
    TC_FENCE_AFTER();
    mbar_wait(XCB, 0);      // completed long ago; fast path

    if (wid < 4){
        int rl = wid*32 + lane;
        int row = row0 + rl;
        const float* xcs = (const float*)(smem + DG_XC) + (size_t)rl*DIM;
        uint32_t woff = (uint32_t)wid << 21;
        float acc = 0.f;
        for (int c0 = 0; c0 < 240; c0 += 32){
            uint32_t pr[32];
            if (c0 < 224){
                LDTM32(pr, tmem + c0 + woff);
                TC_WAIT_LD();
                #pragma unroll
                for (int j = 0; j < 8; j++){
                    float4 c4 = *(const float4*)(xcs + c0 + j*4);
                    acc += __uint_as_float(pr[j*4+0])*c4.x + __uint_as_float(pr[j*4+1])*c4.y
                         + __uint_as_float(pr[j*4+2])*c4.z + __uint_as_float(pr[j*4+3])*c4.w;
                }
            } else {
                LDTM16(pr, tmem + c0 + woff);
                TC_WAIT_LD();
                #pragma unroll
                for (int j = 0; j < 4; j++){
                    float4 c4 = *(const float4*)(xcs + c0 + j*4);
                    acc += __uint_as_float(pr[j*4+0])*c4.x + __uint_as_float(pr[j*4+1])*c4.y
                         + __uint_as_float(pr[j*4+2])*c4.z + __uint_as_float(pr[j*4+3])*c4.w;
                }
            }
        }
        int b = row >> 10, s = row & (SEQ - 1);
        g_diagT[(size_t)s*DIM + b] = acc;
    }
    __syncthreads();
    if (wid == 0) TC_DEALLOC(tmem, 512);
#else
    const int tid = threadIdx.x;
    const int row0 = blockIdx.x * MTILE;
    __shared__ float red[THREADS];
    int r = tid >> 1, half = tid & 1;
    int row = row0 + r;
    float acc = 0.f;
    for (int f = half*120; f < half*120 + 120; f++){
        float p = 0.f;
        for (int e = 0; e < DIM; e++){
            int ch = e >> 5;
            const char* mp = (const char*)g_MTsw + (size_t)ch*B_CH_BYTES + loc_off(f, e & 31);
            p += x[(size_t)row*DIM + e] * (*(const float*)mp);
        }
        acc += p * g_Xc[(size_t)row*DIM + f];
    }
    red[tid] = acc;
    __syncthreads();
    if (half == 0){
        int b = row >> 10, s = row & (SEQ - 1);
        g_diagT[(size_t)s*DIM + b] = red[tid] + red[tid + 1];
    }
#endif
}

// ---------------- K2: fused final ----------------
#define FN_A0   1024u
#define FN_A1   17408u
#define FN_BX0  33792u
#define FN_BX1  64512u
#define FN_BG0  95232u
#define FN_BG1  125952u      // end 156672
#define FN_Y    1024u        // 131072 bytes, over GEMM1 buffers (dead)
#define FN_WO0  156672u
#define FN_WO1  187392u      // end 218112
#define FN_OUT  1024u        // over Y (dead after GEMM2)
#define FN_SMEM 218112u

__global__ void __launch_bounds__(THREADS, 1) __cluster_dims__(1, 1, 1)
final_tc(const float* __restrict__ x,  const float* __restrict__ Wx,
         const float* __restrict__ Wg, const float* __restrict__ Wo,
         const float* __restrict__ bo, float* __restrict__ out){
#if HAS_TC
    extern __shared__ char smem[];
    uint32_t sb = smem_u32(smem);
    const int tid = threadIdx.x;
    const int wid = tid >> 5, lane = tid & 31;
    const int row0 = blockIdx.x * MTILE;
    const uint32_t FUL0 = sb + 8,  FUL1 = sb + 16;
    const uint32_t FRE0 = sb + 24, FRE1 = sb + 32;
    const uint32_t FUL2 = sb + 40, FUL3 = sb + 48;
    const uint32_t FRE2 = sb + 56, FRE3 = sb + 64;
    const uint32_t abuf[2] = { sb + FN_A0,  sb + FN_A1  };
    const uint32_t xbuf[2] = { sb + FN_BX0, sb + FN_BX1 };
    const uint32_t gbuf[2] = { sb + FN_BG0, sb + FN_BG1 };
    const uint32_t obuf[2] = { sb + FN_WO0, sb + FN_WO1 };

    if (wid == 0){ TC_ALLOC(sb + 0, 512); TC_RELINQ(); }
    if (tid == 0){
        MBAR_INIT(FUL0); MBAR_INIT(FUL1); MBAR_INIT(FRE0); MBAR_INIT(FRE1);
        MBAR_INIT(FUL2); MBAR_INIT(FUL3); MBAR_INIT(FRE2); MBAR_INIT(FRE3);
    }
    __syncthreads();
    uint32_t tmem;
    asm volatile("ld.shared.b32 %0, [%1];" : "=r"(tmem) : "r"(sb + 0));

    int isE = 0;
    if (wid == 0) isE = elect_one();

    const uint64_t xg  = __cvta_generic_to_global(g_xsw) + (size_t)blockIdx.x*NCHUNK*A_CH_BYTES;
    const uint64_t wxg = __cvta_generic_to_global(&g_Wsw[0][0]);
    const uint64_t wgg = __cvta_generic_to_global(&g_Wsw[1][0]);
    const uint64_t wog = __cvta_generic_to_global(&g_Wsw[2][0]);

    // ---- GEMM1: D_xk @ tmem+0, D_g @ tmem+256 ----
    if (isE){
        MBAR_EXPECT(FUL0, A_CH_BYTES + 2*B_CH_BYTES);
        BULK_G2S(abuf[0], xg,  A_CH_BYTES, FUL0);
        BULK_G2S(xbuf[0], wxg, B_CH_BYTES, FUL0);
        BULK_G2S(gbuf[0], wgg, B_CH_BYTES, FUL0);
        MBAR_EXPECT(FUL1, A_CH_BYTES + 2*B_CH_BYTES);
        BULK_G2S(abuf[1], xg  + A_CH_BYTES, A_CH_BYTES, FUL1);
        BULK_G2S(xbuf[1], wxg + B_CH_BYTES, B_CH_BYTES, FUL1);
        BULK_G2S(gbuf[1], wgg + B_CH_BYTES, B_CH_BYTES, FUL1);

        uint32_t pf0 = 0, pf1 = 0, pr0 = 0, pr1 = 0;
        #pragma unroll
        for (int ch = 0; ch < NCHUNK; ch++){
            int p = ch & 1;
            uint32_t FUL = p ? FUL1 : FUL0, FRE = p ? FRE1 : FRE0;
            if (ch >= 2){
                if (p){ mbar_wait(FRE, pr1); pr1 ^= 1; } else { mbar_wait(FRE, pr0); pr0 ^= 1; }
                MBAR_EXPECT(FUL, A_CH_BYTES + 2*B_CH_BYTES);
                BULK_G2S(abuf[p], xg  + (size_t)ch*A_CH_BYTES, A_CH_BYTES, FUL);
                BULK_G2S(xbuf[p], wxg + (size_t)ch*B_CH_BYTES, B_CH_BYTES, FUL);
                BULK_G2S(gbuf[p], wgg + (size_t)ch*B_CH_BYTES, B_CH_BYTES, FUL);
            }
            if (p){ mbar_wait(FUL, pf1); pf1 ^= 1; } else { mbar_wait(FUL, pf0); pf0 ^= 1; }
            uint64_t ad = sdesc(abuf[p]), bx = sdesc(xbuf[p]), bg = sdesc(gbuf[p]);
            int nks = (ch == NCHUNK-1) ? 2 : 4;
            for (int ks = 0; ks < nks; ks++){
                uint32_t en = (ch | ks) ? 1u : 0u;
                mma_tf32(tmem + 0,   ad + ks*2, bx + ks*2, IDESC, en);
                mma_tf32(tmem + 256, ad + ks*2, bg + ks*2, IDESC, en);
            }
            TC_COMMIT(FRE);
        }
        mbar_wait(FRE0, pr0);
        mbar_wait(FRE1, pr1);
        // prefetch Wo chunks 0,1 (overlaps epilogue 1)
        MBAR_EXPECT(FUL2, B_CH_BYTES);
        BULK_G2S(obuf[0], wog, B_CH_BYTES, FUL2);
        MBAR_EXPECT(FUL3, B_CH_BYTES);
        BULK_G2S(obuf[1], wog + B_CH_BYTES, B_CH_BYTES, FUL3);
    }
    __syncthreads();
    TC_FENCE_AFTER();

    // ---- epilogue 1: y = xk * sigmoid(g) * diagT[s, c] -> smem Y tile ----
    if (wid < 4){
        int rl = wid*32 + lane;
        int row = row0 + rl;
        int s = row & (SEQ - 1);
        const float* dgr = g_diagT + (size_t)s*DIM;
        uint32_t woff = (uint32_t)wid << 21;
        for (int c0 = 0; c0 < 240; c0 += 32){
            uint32_t xr[32], gr[32];
            if (c0 < 224){
                LDTM32(xr, tmem + 0   + c0 + woff);
                LDTM32(gr, tmem + 256 + c0 + woff);
                TC_WAIT_LD();
                #pragma unroll
                for (int j = 0; j < 8; j++){
                    float4 dv = *(const float4*)(dgr + c0 + j*4);
                    float4 yv;
                    yv.x = __uint_as_float(xr[j*4+0]) * sigf(__uint_as_float(gr[j*4+0])) * dv.x;
                    yv.y = __uint_as_float(xr[j*4+1]) * sigf(__uint_as_float(gr[j*4+1])) * dv.y;
                    yv.z = __uint_as_float(xr[j*4+2]) * sigf(__uint_as_float(gr[j*4+2])) * dv.z;
                    yv.w = __uint_as_float(xr[j*4+3]) * sigf(__uint_as_float(gr[j*4+3])) * dv.w;
                    int k = c0 + j*4;
                    sts_tf32x4(sb + FN_Y + ((uint32_t)(k >> 5) << 14) + loc_off(rl, k & 31), yv);
                }
            } else {
                LDTM16(xr, tmem + 0   + c0 + woff);
                LDTM16(gr, tmem + 256 + c0 + woff);
                TC_WAIT_LD();
                #pragma unroll
                for (int j = 0; j < 4; j++){
                    float4 dv = *(const float4*)(dgr + c0 + j*4);
                    float4 yv;
                    yv.x = __uint_as_float(xr[j*4+0]) * sigf(__uint_as_float(gr[j*4+0])) * dv.x;
                    yv.y = __uint_as_float(xr[j*4+1]) * sigf(__uint_as_float(gr[j*4+1])) * dv.y;
                    yv.z = __uint_as_float(xr[j*4+2]) * sigf(__uint_as_float(gr[j*4+2])) * dv.z;
                    yv.w = __uint_as_float(xr[j*4+3]) * sigf(__uint_as_float(gr[j*4+3])) * dv.w;
                    int k = c0 + j*4;
                    sts_tf32x4(sb + FN_Y + ((uint32_t)(k >> 5) << 14) + loc_off(rl, k & 31), yv);
                }
            }
        }
        TC_FENCE_BEFORE();
    }
    FENCE_ASYNC();
    __syncthreads();
    TC_FENCE_AFTER();

    // ---- GEMM2: D_o @ tmem+0, A = Y smem, B = Wo chunks ----
    if (isE){
        FENCE_ASYNC();
        uint32_t pf2 = 0, pf3 = 0, pr2 = 0, pr3 = 0;
        #pragma unroll
        for (int ch = 0; ch < NCHUNK; ch++){
            int p = ch & 1;
            uint32_t FUL = p ? FUL3 : FUL2, FRE = p ? FRE3 : FRE2;
            if (ch >= 2){
                if (p){ mbar_wait(FRE, pr3); pr3 ^= 1; } else { mbar_wait(FRE, pr2); pr2 ^= 1; }
                MBAR_EXPECT(FUL, B_CH_BYTES);
                BULK_G2S(obuf[p], wog + (size_t)ch*B_CH_BYTES, B_CH_BYTES, FUL);
            }
            if (p){ mbar_wait(FUL, pf3); pf3 ^= 1; } else { mbar_wait(FUL, pf2); pf2 ^= 1; }
            uint64_t yd = sdesc(sb + FN_Y), wd = sdesc(obuf[p]);
            int nks = (ch == NCHUNK-1) ? 2 : 4;
            for (int ks = 0; ks < nks; ks++){
                int gks = ch*4 + ks;
                uint64_t ao = (uint64_t)((gks >> 2)*1024 + (gks & 3)*2);
                mma_tf32(tmem + 0, yd + ao, wd + ks*2, IDESC, (ch | ks) ? 1u : 0u);
            }
            TC_COMMIT(FRE);
        }
        mbar_wait(FRE2, pr2);
        mbar_wait(FRE3, pr3);
    }
    __syncthreads();
    TC_FENCE_AFTER();

    // ---- epilogue 2: + bias -> smem row-major -> bulk s2g ----
    float* outs = (float*)(smem + FN_OUT);
    if (wid < 4){
        int rl = wid*32 + lane;
        uint32_t woff = (uint32_t)wid << 21;
        for (int c0 = 0; c0 < 240; c0 += 32){
            uint32_t orr[32];
            if (c0 < 224){
                LDTM32(orr, tmem + c0 + woff);
                TC_WAIT_LD();
                #pragma unroll
                for (int j = 0; j < 8; j++){
                    float4 bv = *(const float4*)(bo + c0 + j*4);
                    *(float4*)(outs + (size_t)rl*DIM + c0 + j*4) =
                        make_float4(__uint_as_float(orr[j*4+0]) + bv.x,
                                    __uint_as_float(orr[j*4+1]) + bv.y,
                                    __uint_as_float(orr[j*4+2]) + bv.z,
                                    __uint_as_float(orr[j*4+3]) + bv.w);
                }
            } else {
                LDTM16(orr, tmem + c0 + woff);
                TC_WAIT_LD();
                #pragma unroll
                for (int j = 0; j < 4; j++){
                    float4 bv = *(const float4*)(bo + c0 + j*4);
                    *(float4*)(outs + (size_t)rl*DIM + c0 + j*4) =
                        make_float4(__uint_as_float(orr[j*4+0]) + bv.x,
                                    __uint_as_float(orr[j*4+1]) + bv.y,
                                    __uint_as_float(orr[j*4+2]) + bv.z,
                                    __uint_as_float(orr[j*4+3]) + bv.w);
                }
            }
        }
    }
    __syncthreads();
    if (isE){
        FENCE_ASYNC();
        uint64_t og = __cvta_generic_to_global(out) + (size_t)row0*DIM*4;
        BULK_S2G(og, sb + FN_OUT, XC_BYTES);
        BULK_COMMIT();
        BULK_WAIT0();
    }
    __syncthreads();
    if (wid == 0) TC_DEALLOC(tmem, 512);
#else
    extern __shared__ char smem[];
    float* ys = (float*)(smem + 1024);
    const int tid = threadIdx.x;
    const int row0 = blockIdx.x * MTILE;
    for (int idx = tid; idx < MTILE*DIM; idx += THREADS){
        int r = idx / DIM, c = idx % DIM;
        int row = row0 + r;
        const float* xr = x + (size_t)row*DIM;
        float xk = 0.f, gp = 0.f;
        for (int e = 0; e < DIM; e++){
            float xe = xr[e];
            xk += xe * Wx[(size_t)c*DIM + e];
            gp += xe * Wg[(size_t)c*DIM + e];
        }
        int s = row & (SEQ - 1);
        ys[(size_t)r*DIM + c] = xk * sigf(gp) * g_diagT[(size_t)s*DIM + c];
    }
    __syncthreads();
    for (int idx = tid; idx < MTILE*DIM; idx += THREADS){
        int r = idx / DIM, c = idx % DIM;
        float acc = bo[c];
        const float* yr = ys + (size_t)r*DIM;
        for (int d = 0; d < DIM; d++) acc += yr[d] * Wo[(size_t)c*DIM + d];
        out[((size_t)(row0 + r))*DIM + c] = acc;
    }
#endif
}

// ---------------- launch ----------------
extern "C" void kernel_launch(void* const* d_in, const int* in_sizes, int n_in,
                              void* d_out, int out_size){
    const float* x     = (const float*)d_in[0];
    const float* Wx    = (const float*)d_in[1];
    const float* Wk    = (const float*)d_in[2];
    const float* Wv    = (const float*)d_in[3];
    const float* Wg    = (const float*)d_in[4];
    const float* Wo    = (const float*)d_in[5];
    const float* bo    = (const float*)d_in[6];
    const float* dmask = (const float*)d_in[7];
    float* out = (float*)d_out;
    (void)in_sizes; (void)n_in; (void)out_size;

    cudaFuncSetAttribute(diag_tc,  cudaFuncAttributeMaxDynamicSharedMemorySize, DG_SMEM);
    cudaFuncSetAttribute(final_tc, cudaFuncAttributeMaxDynamicSharedMemorySize, FN_SMEM);

    weights_swz_kernel<<<dim3((DIM*DIM + 255)/256, 3), 256>>>(Wx, Wg, Wo);
    compute_MT_kernel<<<dim3(15, 15), dim3(16, 16)>>>(Wk, Wv, dmask);
    cumsum_kernel<<<(NB*DIM + 255)/256, 256>>>(x);
    xsw_kernel<<<(NROW*60 + 255)/256, 256>>>(x);
    diag_tc<<<NROW/MTILE, THREADS, DG_SMEM>>>(x);
    final_tc<<<NROW/MTILE, THREADS, FN_SMEM>>>(x, Wx, Wg, Wo, bo, out);
}